// round 1
// baseline (speedup 1.0000x reference)
#include <cuda_runtime.h>
#include <cuda_bf16.h>

#define N_NODES 50000
#define N_EDGES 800000
#define D 128
#define BN_EPS 1e-5f

// Scratch (static device allocations are permitted; no runtime alloc)
__device__ float g_Ah[N_NODES * D];
__device__ float g_Bh[N_NODES * D];
__device__ float g_Ch[N_NODES * D];
__device__ float g_hpre[N_NODES * D];   // Dh, then += scatter(m)
__device__ float g_sum[D];
__device__ float g_sumsq[D];

// ---------------------------------------------------------------------------
// K0: zero BN stat accumulators
// ---------------------------------------------------------------------------
__global__ void init_stats_kernel() {
    int t = threadIdx.x;
    if (t < D) { g_sum[t] = 0.f; g_sumsq[t] = 0.f; }
}

// ---------------------------------------------------------------------------
// Shared GEMM core: C[128 rows x 128 cols] = A_rows . W^T  (both K-fastest)
// smem layout: k-major with pad 129 (conflict-free STS on transpose-store and
// conflict-free LDS with thread tile r=ty+16i, c=tx+16j)
// ---------------------------------------------------------------------------

// K1: node projections. blockIdx.y selects WA/WB/WC/WD -> Ah/Bh/Ch/hpre
__global__ void __launch_bounds__(256)
node_gemm_kernel(const float* __restrict__ h,
                 const float* __restrict__ WA, const float* __restrict__ WB,
                 const float* __restrict__ WC, const float* __restrict__ WD) {
    __shared__ float As[32 * 129];
    __shared__ float Bs[32 * 129];

    const float* Wsel[4] = {WA, WB, WC, WD};
    float* Osel[4] = {g_Ah, g_Bh, g_Ch, g_hpre};
    const float* __restrict__ W = Wsel[blockIdx.y];
    float* __restrict__ out = Osel[blockIdx.y];

    const int row0 = blockIdx.x * 128;
    const int tid = threadIdx.x;
    const int tx = tid & 15;
    const int ty = tid >> 4;

    float acc[8][8];
#pragma unroll
    for (int i = 0; i < 8; i++)
#pragma unroll
        for (int j = 0; j < 8; j++) acc[i][j] = 0.f;

    for (int kc = 0; kc < D; kc += 32) {
#pragma unroll
        for (int l = 0; l < 4; l++) {
            int idx = tid + l * 256;          // 0..1023
            int r = idx >> 3;                 // 0..127
            int k4 = idx & 7;                 // 0..7  (float4 index)
            int row = row0 + r;
            float4 v = make_float4(0.f, 0.f, 0.f, 0.f);
            if (row < N_NODES) v = *(const float4*)&h[row * D + kc + k4 * 4];
            As[(k4 * 4 + 0) * 129 + r] = v.x;
            As[(k4 * 4 + 1) * 129 + r] = v.y;
            As[(k4 * 4 + 2) * 129 + r] = v.z;
            As[(k4 * 4 + 3) * 129 + r] = v.w;
            float4 w = *(const float4*)&W[r * D + kc + k4 * 4]; // W row r = output col
            Bs[(k4 * 4 + 0) * 129 + r] = w.x;
            Bs[(k4 * 4 + 1) * 129 + r] = w.y;
            Bs[(k4 * 4 + 2) * 129 + r] = w.z;
            Bs[(k4 * 4 + 3) * 129 + r] = w.w;
        }
        __syncthreads();
#pragma unroll
        for (int k = 0; k < 32; k++) {
            float a[8], b[8];
#pragma unroll
            for (int i = 0; i < 8; i++) a[i] = As[k * 129 + ty + 16 * i];
#pragma unroll
            for (int j = 0; j < 8; j++) b[j] = Bs[k * 129 + tx + 16 * j];
#pragma unroll
            for (int i = 0; i < 8; i++)
#pragma unroll
                for (int j = 0; j < 8; j++) acc[i][j] = fmaf(a[i], b[j], acc[i][j]);
        }
        __syncthreads();
    }

#pragma unroll
    for (int i = 0; i < 8; i++) {
        int row = row0 + ty + 16 * i;
        if (row < N_NODES) {
#pragma unroll
            for (int j = 0; j < 8; j++) out[row * D + tx + 16 * j] = acc[i][j];
        }
    }
}

// K2: edge GEMM e@WE^T fused with gate + message + scatter-add. E % 128 == 0.
__global__ void __launch_bounds__(256)
edge_kernel(const float* __restrict__ e, const float* __restrict__ WE,
            const int* __restrict__ src, const int* __restrict__ dst,
            float* __restrict__ e_out) {
    __shared__ float As[32 * 129];
    __shared__ float Bs[32 * 129];
    __shared__ int s_src[128];
    __shared__ int s_dst[128];

    const int e0 = blockIdx.x * 128;
    const int tid = threadIdx.x;
    const int tx = tid & 15;
    const int ty = tid >> 4;

    if (tid < 128) { s_src[tid] = src[e0 + tid]; s_dst[tid] = dst[e0 + tid]; }

    float acc[8][8];
#pragma unroll
    for (int i = 0; i < 8; i++)
#pragma unroll
        for (int j = 0; j < 8; j++) acc[i][j] = 0.f;

    for (int kc = 0; kc < D; kc += 32) {
#pragma unroll
        for (int l = 0; l < 4; l++) {
            int idx = tid + l * 256;
            int r = idx >> 3;
            int k4 = idx & 7;
            float4 v = *(const float4*)&e[(size_t)(e0 + r) * D + kc + k4 * 4];
            As[(k4 * 4 + 0) * 129 + r] = v.x;
            As[(k4 * 4 + 1) * 129 + r] = v.y;
            As[(k4 * 4 + 2) * 129 + r] = v.z;
            As[(k4 * 4 + 3) * 129 + r] = v.w;
            float4 w = *(const float4*)&WE[r * D + kc + k4 * 4];
            Bs[(k4 * 4 + 0) * 129 + r] = w.x;
            Bs[(k4 * 4 + 1) * 129 + r] = w.y;
            Bs[(k4 * 4 + 2) * 129 + r] = w.z;
            Bs[(k4 * 4 + 3) * 129 + r] = w.w;
        }
        __syncthreads();
#pragma unroll
        for (int k = 0; k < 32; k++) {
            float a[8], b[8];
#pragma unroll
            for (int i = 0; i < 8; i++) a[i] = As[k * 129 + ty + 16 * i];
#pragma unroll
            for (int j = 0; j < 8; j++) b[j] = Bs[k * 129 + tx + 16 * j];
#pragma unroll
            for (int i = 0; i < 8; i++)
#pragma unroll
                for (int j = 0; j < 8; j++) acc[i][j] = fmaf(a[i], b[j], acc[i][j]);
        }
        __syncthreads();
    }

    // Epilogue: e_new store + sigmoid gate + gated message + scatter-add
#pragma unroll
    for (int i = 0; i < 8; i++) {
        int er = ty + 16 * i;
        size_t edge = (size_t)(e0 + er);
        int se = s_src[er];
        int de = s_dst[er];
        const float* __restrict__ ah = &g_Ah[(size_t)se * D];
        const float* __restrict__ bh = &g_Bh[(size_t)de * D];
        const float* __restrict__ ch = &g_Ch[(size_t)se * D];
        float* __restrict__ hp = &g_hpre[(size_t)de * D];
#pragma unroll
        for (int j = 0; j < 8; j++) {
            int c = tx + 16 * j;
            float en = acc[i][j];
            e_out[edge * D + c] = en;
            float x = ah[c] + bh[c] + en;
            float gate = 1.f / (1.f + __expf(-x));
            atomicAdd(&hp[c], ch[c] * gate);
        }
    }
}

// K3a: per-column sum / sumsq over hpre
__global__ void __launch_bounds__(256)
bn_stats_kernel() {
    __shared__ float ssum[256];
    __shared__ float ssq[256];
    const int c = threadIdx.x & 127;
    const int half = threadIdx.x >> 7;
    float s = 0.f, s2 = 0.f;
    for (int r = blockIdx.x * 2 + half; r < N_NODES; r += gridDim.x * 2) {
        float x = g_hpre[(size_t)r * D + c];
        s += x;
        s2 += x * x;
    }
    ssum[threadIdx.x] = s;
    ssq[threadIdx.x] = s2;
    __syncthreads();
    if (half == 0) {
        atomicAdd(&g_sum[c], ssum[c] + ssum[c + 128]);
        atomicAdd(&g_sumsq[c], ssq[c] + ssq[c + 128]);
    }
}

// K3b: normalize + affine + relu -> h_new
__global__ void __launch_bounds__(256)
bn_apply_kernel(const float* __restrict__ gamma, const float* __restrict__ beta,
                float* __restrict__ h_out) {
    int idx = blockIdx.x * blockDim.x + threadIdx.x;
    if (idx >= N_NODES * D) return;
    int c = idx & 127;
    const float invN = 1.f / (float)N_NODES;
    float mean = g_sum[c] * invN;
    float var = g_sumsq[c] * invN - mean * mean;
    float x = (g_hpre[idx] - mean) * rsqrtf(var + BN_EPS) * gamma[c] + beta[c];
    h_out[idx] = fmaxf(x, 0.f);
}

// ---------------------------------------------------------------------------
extern "C" void kernel_launch(void* const* d_in, const int* in_sizes, int n_in,
                              void* d_out, int out_size) {
    const float* h     = (const float*)d_in[0];
    const float* e     = (const float*)d_in[1];
    const float* WA    = (const float*)d_in[2];
    const float* WB    = (const float*)d_in[3];
    const float* WC    = (const float*)d_in[4];
    const float* WD    = (const float*)d_in[5];
    const float* WE    = (const float*)d_in[6];
    const float* gamma = (const float*)d_in[7];
    const float* beta  = (const float*)d_in[8];
    const int*   src   = (const int*)d_in[9];
    const int*   dst   = (const int*)d_in[10];

    float* h_out = (float*)d_out;                       // [N, D]
    float* e_out = (float*)d_out + (size_t)N_NODES * D; // [E, D]

    init_stats_kernel<<<1, 128>>>();

    dim3 g1((N_NODES + 127) / 128, 4);
    node_gemm_kernel<<<g1, 256>>>(h, WA, WB, WC, WD);

    edge_kernel<<<N_EDGES / 128, 256>>>(e, WE, src, dst, e_out);

    bn_stats_kernel<<<512, 256>>>();

    bn_apply_kernel<<<(N_NODES * D + 255) / 256, 256>>>(gamma, beta, h_out);
}

// round 8
// speedup vs baseline: 1.7820x; 1.7820x over previous
#include <cuda_runtime.h>
#include <cuda_bf16.h>
#include <cstdint>

#define N_NODES 50000
#define N_EDGES 800000
#define DD 128
#define BN_EPS 1e-5f

// ---------------- scratch (static device memory; no runtime alloc) ----------
__device__ float g_Ah[N_NODES * DD];
__device__ float g_Bh[N_NODES * DD];
__device__ float g_Ch[N_NODES * DD];
__device__ float g_hpre[N_NODES * DD];  // h@WD.T then += scatter(m)
__device__ float g_sum[DD];
__device__ float g_sumsq[DD];

// ---------------- smem layout ------------------------------------------------
// bf16 planes, K-major rows, pitch 136 bf16 = 272B (ldmatrix conflict-free:
// 272/16 = 17 ≡ 1 mod 8 -> 8 consecutive rows hit distinct 16B bank-quads)
#define PITCH_B   272
#define PLANE_A   (64 * PITCH_B)    /* 17408: A tile 64 rows x 128 k */
#define PLANE_W   (128 * PITCH_B)   /* 34816: B tile 128 n-rows x 128 k */
#define OFF_SRC   0
#define OFF_DST   256
#define OFF_AHI   1024
#define OFF_ALO   (OFF_AHI + PLANE_A)            /* 18432 */
#define OFF_BHI   (OFF_ALO + PLANE_A)            /* 35840 */
#define OFF_BLO   (OFF_BHI + PLANE_W)            /* 70656 */
#define SMEM_TOTAL (OFF_BLO + PLANE_W)           /* 105472 -> 2 CTAs/SM */
#define OFF_STAGE OFF_AHI                        /* reuse A planes post-MMA */
#define STAGE_PITCH 132                          /* floats */

// ---------------- helpers ----------------------------------------------------
__device__ __forceinline__ uint32_t smem_u32(const void* p) {
    uint32_t a;
    asm("{ .reg .u64 t; cvta.to.shared.u64 t, %1; cvt.u32.u64 %0, t; }"
        : "=r"(a) : "l"(p));
    return a;
}

__device__ __forceinline__ void ldsm4(uint32_t* r, uint32_t addr) {
    asm volatile("ldmatrix.sync.aligned.m8n8.x4.shared.b16 {%0,%1,%2,%3}, [%4];"
                 : "=r"(r[0]), "=r"(r[1]), "=r"(r[2]), "=r"(r[3]) : "r"(addr));
}

__device__ __forceinline__ void mma16816(float* c, const uint32_t* a,
                                         uint32_t b0, uint32_t b1) {
    asm volatile(
        "mma.sync.aligned.m16n8k16.row.col.f32.bf16.bf16.f32 "
        "{%0,%1,%2,%3}, {%4,%5,%6,%7}, {%8,%9}, {%0,%1,%2,%3};"
        : "+f"(c[0]), "+f"(c[1]), "+f"(c[2]), "+f"(c[3])
        : "r"(a[0]), "r"(a[1]), "r"(a[2]), "r"(a[3]), "r"(b0), "r"(b1));
}

__device__ __forceinline__ void red_add4(float* p, float4 v) {
    asm volatile("red.global.add.v4.f32 [%0], {%1,%2,%3,%4};"
                 :: "l"(p), "f"(v.x), "f"(v.y), "f"(v.z), "f"(v.w) : "memory");
}

__device__ __forceinline__ float sigf(float x) {
    return __fdividef(1.f, 1.f + __expf(-x));
}

// convert one float4 (row r, float4-col c4) -> hi/lo bf16 planes
__device__ __forceinline__ void cvt_store(char* smem, int hiOff, int loOff,
                                          int r, int c4, float4 v) {
    __nv_bfloat162 h01 = __floats2bfloat162_rn(v.x, v.y);
    __nv_bfloat162 h23 = __floats2bfloat162_rn(v.z, v.w);
    __nv_bfloat162 l01 = __floats2bfloat162_rn(v.x - __low2float(h01),
                                               v.y - __high2float(h01));
    __nv_bfloat162 l23 = __floats2bfloat162_rn(v.z - __low2float(h23),
                                               v.w - __high2float(h23));
    uint32_t off = (uint32_t)r * PITCH_B + (uint32_t)c4 * 8;
    *reinterpret_cast<uint2*>(smem + hiOff + off) =
        make_uint2(*reinterpret_cast<uint32_t*>(&h01), *reinterpret_cast<uint32_t*>(&h23));
    *reinterpret_cast<uint2*>(smem + loOff + off) =
        make_uint2(*reinterpret_cast<uint32_t*>(&l01), *reinterpret_cast<uint32_t*>(&l23));
}

// one GEMM pass: acc[mt][nt][] += A(offA) . B(offB)^T   (64x128 tile / CTA)
// warp tile 32x32: warp_m in {0,1}, warp_n in {0..3}
__device__ __forceinline__ void gemm_pass(uint32_t sb, int offA, int offB,
                                          int lane, int warp_m, int warp_n,
                                          float acc[2][4][4]) {
    uint32_t aBase = sb + offA +
        (uint32_t)((warp_m * 32 + (lane & 15)) * PITCH_B + (lane >> 4) * 16);
    uint32_t bBase = sb + offB +
        (uint32_t)((warp_n * 32 + (lane & 7) + (lane >> 4) * 8) * PITCH_B +
                   ((lane >> 3) & 1) * 16);
#pragma unroll
    for (int s = 0; s < 8; s++) {
        uint32_t a0[4], a1[4];
        ldsm4(a0, aBase + s * 32);
        ldsm4(a1, aBase + 16 * PITCH_B + s * 32);
#pragma unroll
        for (int ntp = 0; ntp < 2; ntp++) {
            uint32_t b[4];
            ldsm4(b, bBase + ntp * 16 * PITCH_B + s * 32);
            mma16816(acc[0][2 * ntp], a0, b[0], b[1]);
            mma16816(acc[0][2 * ntp + 1], a0, b[2], b[3]);
            mma16816(acc[1][2 * ntp], a1, b[0], b[1]);
            mma16816(acc[1][2 * ntp + 1], a1, b[2], b[3]);
        }
    }
}

// ---------------- K0: zero BN accumulators ----------------------------------
__global__ void init_stats_kernel() {
    int t = threadIdx.x;
    if (t < DD) { g_sum[t] = 0.f; g_sumsq[t] = 0.f; }
}

// ---------------- K1: node projections, 4 weights fused ----------------------
__global__ void __launch_bounds__(256, 2)
node_gemm_kernel(const float* __restrict__ h,
                 const float* __restrict__ WA, const float* __restrict__ WB,
                 const float* __restrict__ WC, const float* __restrict__ WD) {
    extern __shared__ char smem[];
    const uint32_t sb = smem_u32(smem);
    const int tid = threadIdx.x;
    const int lane = tid & 31, wid = tid >> 5;
    const int warp_m = wid & 1, warp_n = wid >> 1;
    const int row0 = blockIdx.x * 64;

    const float* Wsel[4] = {WA, WB, WC, WD};
    float* Osel[4] = {g_Ah, g_Bh, g_Ch, g_hpre};

    // convert A tile (h rows) once
    for (int i = tid; i < 64 * 32; i += 256) {
        int r = i >> 5, c4 = i & 31;
        int grow = row0 + r;
        float4 v = make_float4(0.f, 0.f, 0.f, 0.f);
        if (grow < N_NODES) v = *(const float4*)&h[(size_t)grow * DD + c4 * 4];
        cvt_store(smem, OFF_AHI, OFF_ALO, r, c4, v);
    }

#pragma unroll 1
    for (int w = 0; w < 4; w++) {
        __syncthreads();   // prior readers of B planes done
        const float* __restrict__ W = Wsel[w];
        for (int i = tid; i < 128 * 32; i += 256) {
            int r = i >> 5, c4 = i & 31;
            float4 wv = *(const float4*)&W[r * DD + c4 * 4];
            cvt_store(smem, OFF_BHI, OFF_BLO, r, c4, wv);
        }
        __syncthreads();

        float acc[2][4][4];
#pragma unroll
        for (int a = 0; a < 2; a++)
#pragma unroll
            for (int b = 0; b < 4; b++)
#pragma unroll
                for (int c = 0; c < 4; c++) acc[a][b][c] = 0.f;

        gemm_pass(sb, OFF_AHI, OFF_BHI, lane, warp_m, warp_n, acc);
        gemm_pass(sb, OFF_AHI, OFF_BLO, lane, warp_m, warp_n, acc);
        gemm_pass(sb, OFF_ALO, OFF_BHI, lane, warp_m, warp_n, acc);

        float* __restrict__ out = Osel[w];
#pragma unroll
        for (int mt = 0; mt < 2; mt++)
#pragma unroll
            for (int nt = 0; nt < 4; nt++) {
                int r = row0 + warp_m * 32 + mt * 16 + (lane >> 2);
                int c = warp_n * 32 + nt * 8 + (lane & 3) * 2;
                if (r < N_NODES)
                    *reinterpret_cast<float2*>(&out[(size_t)r * DD + c]) =
                        make_float2(acc[mt][nt][0], acc[mt][nt][1]);
                if (r + 8 < N_NODES)
                    *reinterpret_cast<float2*>(&out[(size_t)(r + 8) * DD + c]) =
                        make_float2(acc[mt][nt][2], acc[mt][nt][3]);
            }
    }
}

// ---------------- K2: edge GEMM + gate + message + scatter -------------------
__global__ void __launch_bounds__(256, 2)
edge_kernel(const float* __restrict__ e, const float* __restrict__ WE,
            const int* __restrict__ src, const int* __restrict__ dst,
            float* __restrict__ e_out) {
    extern __shared__ char smem[];
    const uint32_t sb = smem_u32(smem);
    const int tid = threadIdx.x;
    const int lane = tid & 31, wid = tid >> 5;
    const int warp_m = wid & 1, warp_n = wid >> 1;
    const int e0 = blockIdx.x * 64;

    int* s_src = reinterpret_cast<int*>(smem + OFF_SRC);
    int* s_dst = reinterpret_cast<int*>(smem + OFF_DST);
    if (tid < 64) s_src[tid] = src[e0 + tid];
    else if (tid < 128) s_dst[tid - 64] = dst[e0 + tid - 64];

    for (int i = tid; i < 64 * 32; i += 256) {
        int r = i >> 5, c4 = i & 31;
        float4 v = *(const float4*)&e[(size_t)(e0 + r) * DD + c4 * 4];
        cvt_store(smem, OFF_AHI, OFF_ALO, r, c4, v);
    }
    for (int i = tid; i < 128 * 32; i += 256) {
        int r = i >> 5, c4 = i & 31;
        float4 wv = *(const float4*)&WE[r * DD + c4 * 4];
        cvt_store(smem, OFF_BHI, OFF_BLO, r, c4, wv);
    }
    __syncthreads();

    float acc[2][4][4];
#pragma unroll
    for (int a = 0; a < 2; a++)
#pragma unroll
        for (int b = 0; b < 4; b++)
#pragma unroll
            for (int c = 0; c < 4; c++) acc[a][b][c] = 0.f;

    gemm_pass(sb, OFF_AHI, OFF_BHI, lane, warp_m, warp_n, acc);
    gemm_pass(sb, OFF_AHI, OFF_BLO, lane, warp_m, warp_n, acc);
    gemm_pass(sb, OFF_ALO, OFF_BHI, lane, warp_m, warp_n, acc);

    __syncthreads();   // everyone done reading A planes -> reuse as stage

    float* stage = reinterpret_cast<float*>(smem + OFF_STAGE);
#pragma unroll
    for (int mt = 0; mt < 2; mt++)
#pragma unroll
        for (int nt = 0; nt < 4; nt++) {
            int r = warp_m * 32 + mt * 16 + (lane >> 2);
            int c = warp_n * 32 + nt * 8 + (lane & 3) * 2;
            *reinterpret_cast<float2*>(&stage[r * STAGE_PITCH + c]) =
                make_float2(acc[mt][nt][0], acc[mt][nt][1]);
            *reinterpret_cast<float2*>(&stage[(r + 8) * STAGE_PITCH + c]) =
                make_float2(acc[mt][nt][2], acc[mt][nt][3]);
        }
    __syncthreads();

    // warp-per-edge: coalesced float4 gathers + vector reduction
#pragma unroll 2
    for (int i = 0; i < 8; i++) {
        int r = wid * 8 + i;
        float4 en = *reinterpret_cast<float4*>(&stage[r * STAGE_PITCH + 4 * lane]);
        int sn = s_src[r], dn = s_dst[r];
        const float4 ah = *(const float4*)&g_Ah[(size_t)sn * DD + 4 * lane];
        const float4 bh = *(const float4*)&g_Bh[(size_t)dn * DD + 4 * lane];
        const float4 ch = *(const float4*)&g_Ch[(size_t)sn * DD + 4 * lane];
        *reinterpret_cast<float4*>(&e_out[(size_t)(e0 + r) * DD + 4 * lane]) = en;
        float4 m;
        m.x = ch.x * sigf(ah.x + bh.x + en.x);
        m.y = ch.y * sigf(ah.y + bh.y + en.y);
        m.z = ch.z * sigf(ah.z + bh.z + en.z);
        m.w = ch.w * sigf(ah.w + bh.w + en.w);
        red_add4(&g_hpre[(size_t)dn * DD + 4 * lane], m);
    }
}

// ---------------- K3a: BN stats (float4) ------------------------------------
__global__ void __launch_bounds__(256)
bn_stats_kernel() {
    __shared__ float4 ssum[256];
    __shared__ float4 ssq[256];
    const int l = threadIdx.x & 31;
    const int w = threadIdx.x >> 5;
    float4 s = make_float4(0.f, 0.f, 0.f, 0.f);
    float4 q = make_float4(0.f, 0.f, 0.f, 0.f);
    for (int r = blockIdx.x * 8 + w; r < N_NODES; r += gridDim.x * 8) {
        float4 v = *(const float4*)&g_hpre[(size_t)r * DD + 4 * l];
        s.x += v.x; s.y += v.y; s.z += v.z; s.w += v.w;
        q.x += v.x * v.x; q.y += v.y * v.y; q.z += v.z * v.z; q.w += v.w * v.w;
    }
    ssum[threadIdx.x] = s;
    ssq[threadIdx.x] = q;
    __syncthreads();
    if (threadIdx.x < 32) {
        float4 S = ssum[l], Q = ssq[l];
        for (int ww = 1; ww < 8; ww++) {
            float4 t = ssum[ww * 32 + l];
            S.x += t.x; S.y += t.y; S.z += t.z; S.w += t.w;
            float4 u = ssq[ww * 32 + l];
            Q.x += u.x; Q.y += u.y; Q.z += u.z; Q.w += u.w;
        }
        atomicAdd(&g_sum[4 * l + 0], S.x); atomicAdd(&g_sum[4 * l + 1], S.y);
        atomicAdd(&g_sum[4 * l + 2], S.z); atomicAdd(&g_sum[4 * l + 3], S.w);
        atomicAdd(&g_sumsq[4 * l + 0], Q.x); atomicAdd(&g_sumsq[4 * l + 1], Q.y);
        atomicAdd(&g_sumsq[4 * l + 2], Q.z); atomicAdd(&g_sumsq[4 * l + 3], Q.w);
    }
}

// ---------------- K3b: normalize + affine + relu -----------------------------
__global__ void __launch_bounds__(256)
bn_apply_kernel(const float* __restrict__ gamma, const float* __restrict__ beta,
                float* __restrict__ h_out) {
    int idx4 = blockIdx.x * blockDim.x + threadIdx.x;
    if (idx4 >= N_NODES * DD / 4) return;
    int c4 = idx4 & 31;
    const float invN = 1.f / (float)N_NODES;
    float4 v = *(const float4*)&g_hpre[(size_t)idx4 * 4];
    float4 o;
#pragma unroll
    for (int k = 0; k < 4; k++) {
        float mean = g_sum[4 * c4 + k] * invN;
        float var = g_sumsq[4 * c4 + k] * invN - mean * mean;
        float x = ((&v.x)[k] - mean) * rsqrtf(var + BN_EPS) * gamma[4 * c4 + k] +
                  beta[4 * c4 + k];
        (&o.x)[k] = fmaxf(x, 0.f);
    }
    *reinterpret_cast<float4*>(&h_out[(size_t)idx4 * 4]) = o;
}

// -----------------------------------------------------------------------------
extern "C" void kernel_launch(void* const* d_in, const int* in_sizes, int n_in,
                              void* d_out, int out_size) {
    const float* h     = (const float*)d_in[0];
    const float* e     = (const float*)d_in[1];
    const float* WA    = (const float*)d_in[2];
    const float* WB    = (const float*)d_in[3];
    const float* WC    = (const float*)d_in[4];
    const float* WD    = (const float*)d_in[5];
    const float* WE    = (const float*)d_in[6];
    const float* gamma = (const float*)d_in[7];
    const float* beta  = (const float*)d_in[8];
    const int*   src   = (const int*)d_in[9];
    const int*   dst   = (const int*)d_in[10];

    float* h_out = (float*)d_out;
    float* e_out = (float*)d_out + (size_t)N_NODES * DD;

    cudaFuncSetAttribute(node_gemm_kernel, cudaFuncAttributeMaxDynamicSharedMemorySize, SMEM_TOTAL);
    cudaFuncSetAttribute(edge_kernel, cudaFuncAttributeMaxDynamicSharedMemorySize, SMEM_TOTAL);

    init_stats_kernel<<<1, 128>>>();

    node_gemm_kernel<<<(N_NODES + 63) / 64, 256, SMEM_TOTAL>>>(h, WA, WB, WC, WD);

    edge_kernel<<<N_EDGES / 64, 256, SMEM_TOTAL>>>(e, WE, src, dst, e_out);

    bn_stats_kernel<<<512, 256>>>();

    bn_apply_kernel<<<(N_NODES * DD / 4 + 255) / 256, 256>>>(gamma, beta, h_out);
}

// round 9
// speedup vs baseline: 2.2833x; 1.2813x over previous
#include <cuda_runtime.h>
#include <cuda_bf16.h>
#include <cstdint>

#define N_NODES 50000
#define N_EDGES 800000
#define DD 128
#define BN_EPS 1e-5f

// ---------------- scratch (static device memory; no runtime alloc) ----------
// Interleaved tables: g_AC[node] = {Ah row | Ch row}  (gathered by src)
//                     g_BP[node] = {Bh row | hpre row} (gathered/red by dst)
__device__ __align__(16) float g_AC[N_NODES * 256];
__device__ __align__(16) float g_BP[N_NODES * 256];
__device__ float g_sum[DD];
__device__ float g_sumsq[DD];

// ---------------- smem layout ------------------------------------------------
// bf16 planes, K-major rows, pitch 136 bf16 = 272B (ldmatrix conflict-free)
#define PITCH_B   272
#define PLANE_A   (64 * PITCH_B)    /* 17408 */
#define PLANE_W   (128 * PITCH_B)   /* 34816 */
#define OFF_SRC   0
#define OFF_DST   256
#define OFF_AHI   1024
#define OFF_ALO   (OFF_AHI + PLANE_A)
#define OFF_BHI   (OFF_ALO + PLANE_A)
#define OFF_BLO   (OFF_BHI + PLANE_W)
#define SMEM_TOTAL (OFF_BLO + PLANE_W)   /* 105472 -> 2 CTAs/SM */
#define OFF_STAGE OFF_AHI
#define STAGE_PITCH 132

// Precomputed weight planes: [5 weights][hi/lo][smem-image bytes]
__device__ __align__(16) char g_Wplanes[5][2][PLANE_W];

// ---------------- helpers ----------------------------------------------------
__device__ __forceinline__ uint32_t smem_u32(const void* p) {
    uint32_t a;
    asm("{ .reg .u64 t; cvta.to.shared.u64 t, %1; cvt.u32.u64 %0, t; }"
        : "=r"(a) : "l"(p));
    return a;
}

__device__ __forceinline__ void ldsm4(uint32_t* r, uint32_t addr) {
    asm volatile("ldmatrix.sync.aligned.m8n8.x4.shared.b16 {%0,%1,%2,%3}, [%4];"
                 : "=r"(r[0]), "=r"(r[1]), "=r"(r[2]), "=r"(r[3]) : "r"(addr));
}

__device__ __forceinline__ void mma16816(float* c, const uint32_t* a,
                                         uint32_t b0, uint32_t b1) {
    asm volatile(
        "mma.sync.aligned.m16n8k16.row.col.f32.bf16.bf16.f32 "
        "{%0,%1,%2,%3}, {%4,%5,%6,%7}, {%8,%9}, {%0,%1,%2,%3};"
        : "+f"(c[0]), "+f"(c[1]), "+f"(c[2]), "+f"(c[3])
        : "r"(a[0]), "r"(a[1]), "r"(a[2]), "r"(a[3]), "r"(b0), "r"(b1));
}

__device__ __forceinline__ void red_add4(float* p, float4 v) {
    asm volatile("red.global.add.v4.f32 [%0], {%1,%2,%3,%4};"
                 :: "l"(p), "f"(v.x), "f"(v.y), "f"(v.z), "f"(v.w) : "memory");
}

__device__ __forceinline__ float sigf(float x) {
    return __fdividef(1.f, 1.f + __expf(-x));
}

// convert one float4 (row r, float4-col c4) -> hi/lo bf16 plane images
__device__ __forceinline__ void cvt_store(char* hiP, char* loP,
                                          int r, int c4, float4 v) {
    __nv_bfloat162 h01 = __floats2bfloat162_rn(v.x, v.y);
    __nv_bfloat162 h23 = __floats2bfloat162_rn(v.z, v.w);
    __nv_bfloat162 l01 = __floats2bfloat162_rn(v.x - __low2float(h01),
                                               v.y - __high2float(h01));
    __nv_bfloat162 l23 = __floats2bfloat162_rn(v.z - __low2float(h23),
                                               v.w - __high2float(h23));
    uint32_t off = (uint32_t)r * PITCH_B + (uint32_t)c4 * 8;
    *reinterpret_cast<uint2*>(hiP + off) =
        make_uint2(*reinterpret_cast<uint32_t*>(&h01), *reinterpret_cast<uint32_t*>(&h23));
    *reinterpret_cast<uint2*>(loP + off) =
        make_uint2(*reinterpret_cast<uint32_t*>(&l01), *reinterpret_cast<uint32_t*>(&l23));
}

// one GEMM pass: acc += A(offA) . B(offB)^T  (64x128 tile, warp tile 32x32)
__device__ __forceinline__ void gemm_pass(uint32_t sb, int offA, int offB,
                                          int lane, int warp_m, int warp_n,
                                          float acc[2][4][4]) {
    uint32_t aBase = sb + offA +
        (uint32_t)((warp_m * 32 + (lane & 15)) * PITCH_B + (lane >> 4) * 16);
    uint32_t bBase = sb + offB +
        (uint32_t)((warp_n * 32 + (lane & 7) + (lane >> 4) * 8) * PITCH_B +
                   ((lane >> 3) & 1) * 16);
#pragma unroll
    for (int s = 0; s < 8; s++) {
        uint32_t a0[4], a1[4];
        ldsm4(a0, aBase + s * 32);
        ldsm4(a1, aBase + 16 * PITCH_B + s * 32);
#pragma unroll
        for (int ntp = 0; ntp < 2; ntp++) {
            uint32_t b[4];
            ldsm4(b, bBase + ntp * 16 * PITCH_B + s * 32);
            mma16816(acc[0][2 * ntp], a0, b[0], b[1]);
            mma16816(acc[0][2 * ntp + 1], a0, b[2], b[3]);
            mma16816(acc[1][2 * ntp], a1, b[0], b[1]);
            mma16816(acc[1][2 * ntp + 1], a1, b[2], b[3]);
        }
    }
}

// ---------------- K0: zero BN accumulators ----------------------------------
__global__ void init_stats_kernel() {
    int t = threadIdx.x;
    if (t < DD) { g_sum[t] = 0.f; g_sumsq[t] = 0.f; }
}

// ---------------- Kp: precompute W hi/lo plane images (5 blocks) -------------
__global__ void __launch_bounds__(256)
prep_weights_kernel(const float* __restrict__ WA, const float* __restrict__ WB,
                    const float* __restrict__ WC, const float* __restrict__ WD,
                    const float* __restrict__ WE) {
    const float* Ws[5] = {WA, WB, WC, WD, WE};
    const float* __restrict__ W = Ws[blockIdx.x];
    char* hiP = g_Wplanes[blockIdx.x][0];
    char* loP = g_Wplanes[blockIdx.x][1];
    for (int i = threadIdx.x; i < 128 * 32; i += 256) {
        int r = i >> 5, c4 = i & 31;
        float4 v = *(const float4*)&W[r * DD + c4 * 4];
        cvt_store(hiP, loP, r, c4, v);
    }
}

// copy precomputed W planes into smem (no math)
__device__ __forceinline__ void copy_w_planes(char* smem, int widx, int tid) {
    const float4* hs = (const float4*)g_Wplanes[widx][0];
    const float4* ls = (const float4*)g_Wplanes[widx][1];
    float4* bh = (float4*)(smem + OFF_BHI);
    float4* bl = (float4*)(smem + OFF_BLO);
#pragma unroll 2
    for (int i = tid; i < PLANE_W / 16; i += 256) {
        bh[i] = hs[i];
        bl[i] = ls[i];
    }
}

// ---------------- K1: node projections, 4 weights fused ----------------------
// outputs: WA -> AC[:,0:128], WB -> BP[:,0:128], WC -> AC[:,128:256], WD -> BP[:,128:256]
__global__ void __launch_bounds__(256, 2)
node_gemm_kernel(const float* __restrict__ h) {
    extern __shared__ char smem[];
    const uint32_t sb = smem_u32(smem);
    const int tid = threadIdx.x;
    const int lane = tid & 31, wid = tid >> 5;
    const int warp_m = wid & 1, warp_n = wid >> 1;
    const int row0 = blockIdx.x * 64;

    float* Osel[4] = {g_AC, g_BP, g_AC + 128, g_BP + 128};

    // convert A tile (h rows) once
    for (int i = tid; i < 64 * 32; i += 256) {
        int r = i >> 5, c4 = i & 31;
        int grow = row0 + r;
        float4 v = make_float4(0.f, 0.f, 0.f, 0.f);
        if (grow < N_NODES) v = *(const float4*)&h[(size_t)grow * DD + c4 * 4];
        cvt_store(smem + OFF_AHI, smem + OFF_ALO, r, c4, v);
    }

#pragma unroll 1
    for (int w = 0; w < 4; w++) {
        __syncthreads();   // prior readers of B planes done (and A fill for w=0)
        copy_w_planes(smem, w, tid);
        __syncthreads();

        float acc[2][4][4];
#pragma unroll
        for (int a = 0; a < 2; a++)
#pragma unroll
            for (int b = 0; b < 4; b++)
#pragma unroll
                for (int c = 0; c < 4; c++) acc[a][b][c] = 0.f;

        gemm_pass(sb, OFF_AHI, OFF_BHI, lane, warp_m, warp_n, acc);
        gemm_pass(sb, OFF_AHI, OFF_BLO, lane, warp_m, warp_n, acc);
        gemm_pass(sb, OFF_ALO, OFF_BHI, lane, warp_m, warp_n, acc);

        float* __restrict__ out = Osel[w];
#pragma unroll
        for (int mt = 0; mt < 2; mt++)
#pragma unroll
            for (int nt = 0; nt < 4; nt++) {
                int r = row0 + warp_m * 32 + mt * 16 + (lane >> 2);
                int c = warp_n * 32 + nt * 8 + (lane & 3) * 2;
                if (r < N_NODES)
                    *reinterpret_cast<float2*>(&out[(size_t)r * 256 + c]) =
                        make_float2(acc[mt][nt][0], acc[mt][nt][1]);
                if (r + 8 < N_NODES)
                    *reinterpret_cast<float2*>(&out[(size_t)(r + 8) * 256 + c]) =
                        make_float2(acc[mt][nt][2], acc[mt][nt][3]);
            }
    }
}

// ---------------- K2: persistent edge GEMM + gate + message + scatter --------
__global__ void __launch_bounds__(256, 2)
edge_kernel(const float* __restrict__ e,
            const int* __restrict__ src, const int* __restrict__ dst,
            float* __restrict__ e_out) {
    extern __shared__ char smem[];
    const uint32_t sb = smem_u32(smem);
    const int tid = threadIdx.x;
    const int lane = tid & 31, wid = tid >> 5;
    const int warp_m = wid & 1, warp_n = wid >> 1;

    int* s_src = reinterpret_cast<int*>(smem + OFF_SRC);
    int* s_dst = reinterpret_cast<int*>(smem + OFF_DST);
    float* stage = reinterpret_cast<float*>(smem + OFF_STAGE);

    // WE planes: once per CTA (persistent)
    copy_w_planes(smem, 4, tid);

    for (int t = blockIdx.x; t < N_EDGES / 64; t += gridDim.x) {
        const int e0 = t * 64;
        if (tid < 64) s_src[tid] = src[e0 + tid];
        else if (tid < 128) s_dst[tid - 64] = dst[e0 + tid - 64];

        // convert e tile (streaming loads: evict-first, keep tables in L2)
        for (int i = tid; i < 64 * 32; i += 256) {
            int r = i >> 5, c4 = i & 31;
            float4 v = __ldcs((const float4*)&e[(size_t)(e0 + r) * DD + c4 * 4]);
            cvt_store(smem + OFF_AHI, smem + OFF_ALO, r, c4, v);
        }
        __syncthreads();   // A fill (+ W planes on first iter) visible

        float acc[2][4][4];
#pragma unroll
        for (int a = 0; a < 2; a++)
#pragma unroll
            for (int b = 0; b < 4; b++)
#pragma unroll
                for (int c = 0; c < 4; c++) acc[a][b][c] = 0.f;

        gemm_pass(sb, OFF_AHI, OFF_BHI, lane, warp_m, warp_n, acc);
        gemm_pass(sb, OFF_AHI, OFF_BLO, lane, warp_m, warp_n, acc);
        gemm_pass(sb, OFF_ALO, OFF_BHI, lane, warp_m, warp_n, acc);

        __syncthreads();   // all warps done reading A planes -> reuse as stage

#pragma unroll
        for (int mt = 0; mt < 2; mt++)
#pragma unroll
            for (int nt = 0; nt < 4; nt++) {
                int r = warp_m * 32 + mt * 16 + (lane >> 2);
                int c = warp_n * 32 + nt * 8 + (lane & 3) * 2;
                *reinterpret_cast<float2*>(&stage[r * STAGE_PITCH + c]) =
                    make_float2(acc[mt][nt][0], acc[mt][nt][1]);
                *reinterpret_cast<float2*>(&stage[(r + 8) * STAGE_PITCH + c]) =
                    make_float2(acc[mt][nt][2], acc[mt][nt][3]);
            }
        __syncthreads();

        // warp-per-edge: coalesced float4 gathers (L2-resident tables) + red
#pragma unroll 2
        for (int i = 0; i < 8; i++) {
            int r = wid * 8 + i;
            float4 en = *reinterpret_cast<float4*>(&stage[r * STAGE_PITCH + 4 * lane]);
            int sn = s_src[r], dn = s_dst[r];
            const float* acp = &g_AC[(size_t)sn * 256 + 4 * lane];
            const float* bpp = &g_BP[(size_t)dn * 256 + 4 * lane];
            const float4 ah = *(const float4*)acp;
            const float4 ch = *(const float4*)(acp + 128);
            const float4 bh = *(const float4*)bpp;
            __stcs((float4*)&e_out[(size_t)(e0 + r) * DD + 4 * lane], en);
            float4 m;
            m.x = ch.x * sigf(ah.x + bh.x + en.x);
            m.y = ch.y * sigf(ah.y + bh.y + en.y);
            m.z = ch.z * sigf(ah.z + bh.z + en.z);
            m.w = ch.w * sigf(ah.w + bh.w + en.w);
            red_add4(&g_BP[(size_t)dn * 256 + 128 + 4 * lane], m);
        }
        __syncthreads();   // protect stage/A/s_src before next tile
    }
}

// ---------------- K3a: BN stats over BP[:,128:256] ---------------------------
__global__ void __launch_bounds__(256)
bn_stats_kernel() {
    __shared__ float4 ssum[256];
    __shared__ float4 ssq[256];
    const int l = threadIdx.x & 31;
    const int w = threadIdx.x >> 5;
    float4 s = make_float4(0.f, 0.f, 0.f, 0.f);
    float4 q = make_float4(0.f, 0.f, 0.f, 0.f);
    for (int r = blockIdx.x * 16 + w * 2; r < N_NODES; r += gridDim.x * 16) {
        float4 v = *(const float4*)&g_BP[(size_t)r * 256 + 128 + 4 * l];
        float4 v2 = make_float4(0.f, 0.f, 0.f, 0.f);
        if (r + 1 < N_NODES)
            v2 = *(const float4*)&g_BP[(size_t)(r + 1) * 256 + 128 + 4 * l];
        s.x += v.x + v2.x; s.y += v.y + v2.y; s.z += v.z + v2.z; s.w += v.w + v2.w;
        q.x += v.x * v.x + v2.x * v2.x; q.y += v.y * v.y + v2.y * v2.y;
        q.z += v.z * v.z + v2.z * v2.z; q.w += v.w * v.w + v2.w * v2.w;
    }
    ssum[threadIdx.x] = s;
    ssq[threadIdx.x] = q;
    __syncthreads();
    if (threadIdx.x < 32) {
        float4 S = ssum[l], Q = ssq[l];
        for (int ww = 1; ww < 8; ww++) {
            float4 t = ssum[ww * 32 + l];
            S.x += t.x; S.y += t.y; S.z += t.z; S.w += t.w;
            float4 u = ssq[ww * 32 + l];
            Q.x += u.x; Q.y += u.y; Q.z += u.z; Q.w += u.w;
        }
        atomicAdd(&g_sum[4 * l + 0], S.x); atomicAdd(&g_sum[4 * l + 1], S.y);
        atomicAdd(&g_sum[4 * l + 2], S.z); atomicAdd(&g_sum[4 * l + 3], S.w);
        atomicAdd(&g_sumsq[4 * l + 0], Q.x); atomicAdd(&g_sumsq[4 * l + 1], Q.y);
        atomicAdd(&g_sumsq[4 * l + 2], Q.z); atomicAdd(&g_sumsq[4 * l + 3], Q.w);
    }
}

// ---------------- K3b: normalize + affine + relu -----------------------------
__global__ void __launch_bounds__(256)
bn_apply_kernel(const float* __restrict__ gamma, const float* __restrict__ beta,
                float* __restrict__ h_out) {
    int idx4 = blockIdx.x * blockDim.x + threadIdx.x;
    if (idx4 >= N_NODES * DD / 4) return;
    int row = idx4 >> 5, c4 = idx4 & 31;
    const float invN = 1.f / (float)N_NODES;
    float4 v = *(const float4*)&g_BP[(size_t)row * 256 + 128 + 4 * c4];
    float4 o;
#pragma unroll
    for (int k = 0; k < 4; k++) {
        float mean = g_sum[4 * c4 + k] * invN;
        float var = g_sumsq[4 * c4 + k] * invN - mean * mean;
        float x = ((&v.x)[k] - mean) * rsqrtf(var + BN_EPS) * gamma[4 * c4 + k] +
                  beta[4 * c4 + k];
        (&o.x)[k] = fmaxf(x, 0.f);
    }
    *reinterpret_cast<float4*>(&h_out[(size_t)row * DD + 4 * c4]) = o;
}

// -----------------------------------------------------------------------------
extern "C" void kernel_launch(void* const* d_in, const int* in_sizes, int n_in,
                              void* d_out, int out_size) {
    const float* h     = (const float*)d_in[0];
    const float* e     = (const float*)d_in[1];
    const float* WA    = (const float*)d_in[2];
    const float* WB    = (const float*)d_in[3];
    const float* WC    = (const float*)d_in[4];
    const float* WD    = (const float*)d_in[5];
    const float* WE    = (const float*)d_in[6];
    const float* gamma = (const float*)d_in[7];
    const float* beta  = (const float*)d_in[8];
    const int*   src   = (const int*)d_in[9];
    const int*   dst   = (const int*)d_in[10];

    float* h_out = (float*)d_out;
    float* e_out = (float*)d_out + (size_t)N_NODES * DD;

    cudaFuncSetAttribute(node_gemm_kernel, cudaFuncAttributeMaxDynamicSharedMemorySize, SMEM_TOTAL);
    cudaFuncSetAttribute(edge_kernel, cudaFuncAttributeMaxDynamicSharedMemorySize, SMEM_TOTAL);

    init_stats_kernel<<<1, 128>>>();
    prep_weights_kernel<<<5, 256>>>(WA, WB, WC, WD, WE);

    node_gemm_kernel<<<(N_NODES + 63) / 64, 256, SMEM_TOTAL>>>(h);

    edge_kernel<<<304, 256, SMEM_TOTAL>>>(e, src, dst, e_out);

    bn_stats_kernel<<<512, 256>>>();

    bn_apply_kernel<<<(N_NODES * DD / 4 + 255) / 256, 256>>>(gamma, beta, h_out);
}

// round 10
// speedup vs baseline: 4.0305x; 1.7652x over previous
#include <cuda_runtime.h>
#include <cuda_fp16.h>
#include <cstdint>

#define N_NODES 50000
#define N_EDGES 800000
#define DD 128
#define BN_EPS 1e-5f

// ---------------- scratch (static device memory; no runtime alloc) ----------
// Interleaved tables: g_AC[node] = {Ah row | Ch row}  (gathered by src)
//                     g_BP[node] = {Bh row | hpre row} (gathered/red by dst)
__device__ __align__(16) float g_AC[N_NODES * 256];
__device__ __align__(16) float g_BP[N_NODES * 256];
__device__ float g_sum[DD];
__device__ float g_sumsq[DD];

// ---------------- smem layout ------------------------------------------------
// fp16 planes, K-major rows, pitch 136 halves = 272B (ldmatrix conflict-free)
#define PITCH_B   272
#define PLANE_A   (64 * PITCH_B)    /* 17408 */
#define PLANE_W   (128 * PITCH_B)   /* 34816 */
#define OFF_SRC   0
#define OFF_DST   256
#define OFF_A     1024
#define OFF_B     (OFF_A + PLANE_A)              /* 18432 */
#define SMEM_TOTAL (OFF_B + PLANE_W)             /* 53248 -> 3+ CTAs/SM */
#define OFF_STAGE OFF_A                          /* 32-row fp32 stage overlays A */
#define STAGE_PITCH 132

// Precomputed fp16 weight plane images: [5 weights][smem-image bytes]
__device__ __align__(16) char g_Wplanes[5][PLANE_W];

// ---------------- helpers ----------------------------------------------------
__device__ __forceinline__ uint32_t smem_u32(const void* p) {
    uint32_t a;
    asm("{ .reg .u64 t; cvta.to.shared.u64 t, %1; cvt.u32.u64 %0, t; }"
        : "=r"(a) : "l"(p));
    return a;
}

__device__ __forceinline__ void ldsm4(uint32_t* r, uint32_t addr) {
    asm volatile("ldmatrix.sync.aligned.m8n8.x4.shared.b16 {%0,%1,%2,%3}, [%4];"
                 : "=r"(r[0]), "=r"(r[1]), "=r"(r[2]), "=r"(r[3]) : "r"(addr));
}

__device__ __forceinline__ void mma16816(float* c, const uint32_t* a,
                                         uint32_t b0, uint32_t b1) {
    asm volatile(
        "mma.sync.aligned.m16n8k16.row.col.f32.f16.f16.f32 "
        "{%0,%1,%2,%3}, {%4,%5,%6,%7}, {%8,%9}, {%0,%1,%2,%3};"
        : "+f"(c[0]), "+f"(c[1]), "+f"(c[2]), "+f"(c[3])
        : "r"(a[0]), "r"(a[1]), "r"(a[2]), "r"(a[3]), "r"(b0), "r"(b1));
}

__device__ __forceinline__ void red_add4(float* p, float4 v) {
    asm volatile("red.global.add.v4.f32 [%0], {%1,%2,%3,%4};"
                 :: "l"(p), "f"(v.x), "f"(v.y), "f"(v.z), "f"(v.w) : "memory");
}

__device__ __forceinline__ float sigf(float x) {
    return __fdividef(1.f, 1.f + __expf(-x));
}

// convert one float4 (row r, float4-col c4) -> fp16 plane image
__device__ __forceinline__ void cvt_store16(char* plane, int r, int c4, float4 v) {
    __half2 a = __floats2half2_rn(v.x, v.y);
    __half2 b = __floats2half2_rn(v.z, v.w);
    uint32_t off = (uint32_t)r * PITCH_B + (uint32_t)c4 * 8;
    *reinterpret_cast<uint2*>(plane + off) =
        make_uint2(*reinterpret_cast<uint32_t*>(&a), *reinterpret_cast<uint32_t*>(&b));
}

// GEMM: acc += A . B^T  (64x128 tile, warp tile 32x32)
__device__ __forceinline__ void gemm_pass(uint32_t sb, int offA, int offB,
                                          int lane, int warp_m, int warp_n,
                                          float acc[2][4][4]) {
    uint32_t aBase = sb + offA +
        (uint32_t)((warp_m * 32 + (lane & 15)) * PITCH_B + (lane >> 4) * 16);
    uint32_t bBase = sb + offB +
        (uint32_t)((warp_n * 32 + (lane & 7) + (lane >> 4) * 8) * PITCH_B +
                   ((lane >> 3) & 1) * 16);
#pragma unroll
    for (int s = 0; s < 8; s++) {
        uint32_t a0[4], a1[4];
        ldsm4(a0, aBase + s * 32);
        ldsm4(a1, aBase + 16 * PITCH_B + s * 32);
#pragma unroll
        for (int ntp = 0; ntp < 2; ntp++) {
            uint32_t b[4];
            ldsm4(b, bBase + ntp * 16 * PITCH_B + s * 32);
            mma16816(acc[0][2 * ntp], a0, b[0], b[1]);
            mma16816(acc[0][2 * ntp + 1], a0, b[2], b[3]);
            mma16816(acc[1][2 * ntp], a1, b[0], b[1]);
            mma16816(acc[1][2 * ntp + 1], a1, b[2], b[3]);
        }
    }
}

// ---------------- K0: zero BN accumulators ----------------------------------
__global__ void init_stats_kernel() {
    int t = threadIdx.x;
    if (t < DD) { g_sum[t] = 0.f; g_sumsq[t] = 0.f; }
}

// ---------------- Kp: precompute fp16 W plane images (5 blocks) --------------
__global__ void __launch_bounds__(256)
prep_weights_kernel(const float* __restrict__ WA, const float* __restrict__ WB,
                    const float* __restrict__ WC, const float* __restrict__ WD,
                    const float* __restrict__ WE) {
    const float* Ws[5] = {WA, WB, WC, WD, WE};
    const float* __restrict__ W = Ws[blockIdx.x];
    char* P = g_Wplanes[blockIdx.x];
    for (int i = threadIdx.x; i < 128 * 32; i += 256) {
        int r = i >> 5, c4 = i & 31;
        float4 v = *(const float4*)&W[r * DD + c4 * 4];
        cvt_store16(P, r, c4, v);
    }
}

// copy precomputed W plane into smem (no math)
__device__ __forceinline__ void copy_w_plane(char* smem, int widx, int tid) {
    const float4* ws = (const float4*)g_Wplanes[widx];
    float4* bp = (float4*)(smem + OFF_B);
#pragma unroll 2
    for (int i = tid; i < PLANE_W / 16; i += 256) bp[i] = ws[i];
}

// ---------------- K1: node projections, 4 weights fused ----------------------
// outputs: WA -> AC[:,0:128], WB -> BP[:,0:128], WC -> AC[:,128:256], WD -> BP[:,128:256]
__global__ void __launch_bounds__(256, 3)
node_gemm_kernel(const float* __restrict__ h) {
    extern __shared__ char smem[];
    const uint32_t sb = smem_u32(smem);
    const int tid = threadIdx.x;
    const int lane = tid & 31, wid = tid >> 5;
    const int warp_m = wid & 1, warp_n = wid >> 1;
    const int row0 = blockIdx.x * 64;

    float* Osel[4] = {g_AC, g_BP, g_AC + 128, g_BP + 128};

    // convert A tile (h rows) once
    for (int i = tid; i < 64 * 32; i += 256) {
        int r = i >> 5, c4 = i & 31;
        int grow = row0 + r;
        float4 v = make_float4(0.f, 0.f, 0.f, 0.f);
        if (grow < N_NODES) v = __ldcs((const float4*)&h[(size_t)grow * DD + c4 * 4]);
        cvt_store16(smem + OFF_A, r, c4, v);
    }

#pragma unroll 1
    for (int w = 0; w < 4; w++) {
        __syncthreads();   // prior readers of B plane done (and A fill for w=0)
        copy_w_plane(smem, w, tid);
        __syncthreads();

        float acc[2][4][4];
#pragma unroll
        for (int a = 0; a < 2; a++)
#pragma unroll
            for (int b = 0; b < 4; b++)
#pragma unroll
                for (int c = 0; c < 4; c++) acc[a][b][c] = 0.f;

        gemm_pass(sb, OFF_A, OFF_B, lane, warp_m, warp_n, acc);

        float* __restrict__ out = Osel[w];
#pragma unroll
        for (int mt = 0; mt < 2; mt++)
#pragma unroll
            for (int nt = 0; nt < 4; nt++) {
                int r = row0 + warp_m * 32 + mt * 16 + (lane >> 2);
                int c = warp_n * 32 + nt * 8 + (lane & 3) * 2;
                if (r < N_NODES)
                    *reinterpret_cast<float2*>(&out[(size_t)r * 256 + c]) =
                        make_float2(acc[mt][nt][0], acc[mt][nt][1]);
                if (r + 8 < N_NODES)
                    *reinterpret_cast<float2*>(&out[(size_t)(r + 8) * 256 + c]) =
                        make_float2(acc[mt][nt][2], acc[mt][nt][3]);
            }
    }
}

// ---------------- K2: persistent edge GEMM + gate + message + scatter --------
__global__ void __launch_bounds__(256, 3)
edge_kernel(const float* __restrict__ e,
            const int* __restrict__ src, const int* __restrict__ dst,
            float* __restrict__ e_out) {
    extern __shared__ char smem[];
    const uint32_t sb = smem_u32(smem);
    const int tid = threadIdx.x;
    const int lane = tid & 31, wid = tid >> 5;
    const int warp_m = wid & 1, warp_n = wid >> 1;

    int* s_src = reinterpret_cast<int*>(smem + OFF_SRC);
    int* s_dst = reinterpret_cast<int*>(smem + OFF_DST);
    float* stage = reinterpret_cast<float*>(smem + OFF_STAGE);

    // WE plane: once per CTA (persistent)
    copy_w_plane(smem, 4, tid);

    for (int t = blockIdx.x; t < N_EDGES / 64; t += gridDim.x) {
        const int e0 = t * 64;
        if (tid < 64) s_src[tid] = src[e0 + tid];
        else if (tid < 128) s_dst[tid - 64] = dst[e0 + tid - 64];

        // convert e tile (streaming loads: evict-first, keep tables in L2)
        for (int i = tid; i < 64 * 32; i += 256) {
            int r = i >> 5, c4 = i & 31;
            float4 v = __ldcs((const float4*)&e[(size_t)(e0 + r) * DD + c4 * 4]);
            cvt_store16(smem + OFF_A, r, c4, v);
        }
        __syncthreads();   // A fill (+ W plane on first iter) visible

        float acc[2][4][4];
#pragma unroll
        for (int a = 0; a < 2; a++)
#pragma unroll
            for (int b = 0; b < 4; b++)
#pragma unroll
                for (int c = 0; c < 4; c++) acc[a][b][c] = 0.f;

        gemm_pass(sb, OFF_A, OFF_B, lane, warp_m, warp_n, acc);

        __syncthreads();   // all warps done reading A plane -> reuse as stage

        // two 32-row epilogue rounds (stage overlays the 17 KB A plane)
#pragma unroll 1
        for (int half = 0; half < 2; half++) {
            if (warp_m == half) {
#pragma unroll
                for (int mt = 0; mt < 2; mt++)
#pragma unroll
                    for (int nt = 0; nt < 4; nt++) {
                        int r = mt * 16 + (lane >> 2);
                        int c = warp_n * 32 + nt * 8 + (lane & 3) * 2;
                        *reinterpret_cast<float2*>(&stage[r * STAGE_PITCH + c]) =
                            make_float2(acc[mt][nt][0], acc[mt][nt][1]);
                        *reinterpret_cast<float2*>(&stage[(r + 8) * STAGE_PITCH + c]) =
                            make_float2(acc[mt][nt][2], acc[mt][nt][3]);
                    }
            }
            __syncthreads();

            // warp-per-edge: coalesced float4 gathers (L2-resident tables) + red
#pragma unroll
            for (int i = 0; i < 4; i++) {
                int r32 = wid * 4 + i;
                int r = half * 32 + r32;
                float4 en = *reinterpret_cast<float4*>(&stage[r32 * STAGE_PITCH + 4 * lane]);
                int sn = s_src[r], dn = s_dst[r];
                const float* acp = &g_AC[(size_t)sn * 256 + 4 * lane];
                const float* bpp = &g_BP[(size_t)dn * 256 + 4 * lane];
                const float4 ah = *(const float4*)acp;
                const float4 ch = *(const float4*)(acp + 128);
                const float4 bh = *(const float4*)bpp;
                __stcs((float4*)&e_out[(size_t)(e0 + r) * DD + 4 * lane], en);
                float4 m;
                m.x = ch.x * sigf(ah.x + bh.x + en.x);
                m.y = ch.y * sigf(ah.y + bh.y + en.y);
                m.z = ch.z * sigf(ah.z + bh.z + en.z);
                m.w = ch.w * sigf(ah.w + bh.w + en.w);
                red_add4(&g_BP[(size_t)dn * 256 + 128 + 4 * lane], m);
            }
            __syncthreads();   // stage reuse / next-tile A overwrite
        }
    }
}

// ---------------- K3a: BN stats over BP[:,128:256] ---------------------------
__global__ void __launch_bounds__(256)
bn_stats_kernel() {
    __shared__ float4 ssum[256];
    __shared__ float4 ssq[256];
    const int l = threadIdx.x & 31;
    const int w = threadIdx.x >> 5;
    float4 s = make_float4(0.f, 0.f, 0.f, 0.f);
    float4 q = make_float4(0.f, 0.f, 0.f, 0.f);
    for (int r = blockIdx.x * 16 + w * 2; r < N_NODES; r += gridDim.x * 16) {
        float4 v = *(const float4*)&g_BP[(size_t)r * 256 + 128 + 4 * l];
        float4 v2 = make_float4(0.f, 0.f, 0.f, 0.f);
        if (r + 1 < N_NODES)
            v2 = *(const float4*)&g_BP[(size_t)(r + 1) * 256 + 128 + 4 * l];
        s.x += v.x + v2.x; s.y += v.y + v2.y; s.z += v.z + v2.z; s.w += v.w + v2.w;
        q.x += v.x * v.x + v2.x * v2.x; q.y += v.y * v.y + v2.y * v2.y;
        q.z += v.z * v.z + v2.z * v2.z; q.w += v.w * v.w + v2.w * v2.w;
    }
    ssum[threadIdx.x] = s;
    ssq[threadIdx.x] = q;
    __syncthreads();
    if (threadIdx.x < 32) {
        float4 S = ssum[l], Q = ssq[l];
        for (int ww = 1; ww < 8; ww++) {
            float4 t = ssum[ww * 32 + l];
            S.x += t.x; S.y += t.y; S.z += t.z; S.w += t.w;
            float4 u = ssq[ww * 32 + l];
            Q.x += u.x; Q.y += u.y; Q.z += u.z; Q.w += u.w;
        }
        atomicAdd(&g_sum[4 * l + 0], S.x); atomicAdd(&g_sum[4 * l + 1], S.y);
        atomicAdd(&g_sum[4 * l + 2], S.z); atomicAdd(&g_sum[4 * l + 3], S.w);
        atomicAdd(&g_sumsq[4 * l + 0], Q.x); atomicAdd(&g_sumsq[4 * l + 1], Q.y);
        atomicAdd(&g_sumsq[4 * l + 2], Q.z); atomicAdd(&g_sumsq[4 * l + 3], Q.w);
    }
}

// ---------------- K3b: normalize + affine + relu -----------------------------
__global__ void __launch_bounds__(256)
bn_apply_kernel(const float* __restrict__ gamma, const float* __restrict__ beta,
                float* __restrict__ h_out) {
    int idx4 = blockIdx.x * blockDim.x + threadIdx.x;
    if (idx4 >= N_NODES * DD / 4) return;
    int row = idx4 >> 5, c4 = idx4 & 31;
    const float invN = 1.f / (float)N_NODES;
    float4 v = *(const float4*)&g_BP[(size_t)row * 256 + 128 + 4 * c4];
    float4 o;
#pragma unroll
    for (int k = 0; k < 4; k++) {
        float mean = g_sum[4 * c4 + k] * invN;
        float var = g_sumsq[4 * c4 + k] * invN - mean * mean;
        float x = ((&v.x)[k] - mean) * rsqrtf(var + BN_EPS) * gamma[4 * c4 + k] +
                  beta[4 * c4 + k];
        (&o.x)[k] = fmaxf(x, 0.f);
    }
    *reinterpret_cast<float4*>(&h_out[(size_t)row * DD + 4 * c4]) = o;
}

// -----------------------------------------------------------------------------
extern "C" void kernel_launch(void* const* d_in, const int* in_sizes, int n_in,
                              void* d_out, int out_size) {
    const float* h     = (const float*)d_in[0];
    const float* e     = (const float*)d_in[1];
    const float* WA    = (const float*)d_in[2];
    const float* WB    = (const float*)d_in[3];
    const float* WC    = (const float*)d_in[4];
    const float* WD    = (const float*)d_in[5];
    const float* WE    = (const float*)d_in[6];
    const float* gamma = (const float*)d_in[7];
    const float* beta  = (const float*)d_in[8];
    const int*   src   = (const int*)d_in[9];
    const int*   dst   = (const int*)d_in[10];

    float* h_out = (float*)d_out;
    float* e_out = (float*)d_out + (size_t)N_NODES * DD;

    cudaFuncSetAttribute(node_gemm_kernel, cudaFuncAttributeMaxDynamicSharedMemorySize, SMEM_TOTAL);
    cudaFuncSetAttribute(edge_kernel, cudaFuncAttributeMaxDynamicSharedMemorySize, SMEM_TOTAL);

    init_stats_kernel<<<1, 128>>>();
    prep_weights_kernel<<<5, 256>>>(WA, WB, WC, WD, WE);

    node_gemm_kernel<<<(N_NODES + 63) / 64, 256, SMEM_TOTAL>>>(h);

    edge_kernel<<<444, 256, SMEM_TOTAL>>>(e, src, dst, e_out);

    bn_stats_kernel<<<512, 256>>>();

    bn_apply_kernel<<<(N_NODES * DD / 4 + 255) / 256, 256>>>(gamma, beta, h_out);
}

// round 11
// speedup vs baseline: 4.6473x; 1.1530x over previous
#include <cuda_runtime.h>
#include <cuda_fp16.h>
#include <cstdint>

#define N_NODES 50000
#define N_EDGES 800000
#define DD 128
#define BN_EPS 1e-5f

// ---------------- scratch (static device memory; no runtime alloc) ----------
// g_ACh[node]: 256 halves = 32 groups of {Ah[4g..4g+3], Ch[4g..4g+3]}  (by src)
// g_Bhh[node]: 128 halves = Bh row                                      (by dst)
// g_hpre[node]: 128 floats = h@WD.T then += scatter(m)                  (by dst)
__device__ __align__(16) __half g_ACh[N_NODES * 256];
__device__ __align__(16) __half g_Bhh[N_NODES * 128];
__device__ __align__(16) float  g_hpre[N_NODES * 128];
__device__ float g_sum[DD];
__device__ float g_sumsq[DD];

// ---------------- smem layout ------------------------------------------------
// fp16 planes, K-major rows, pitch 136 halves = 272B (ldmatrix conflict-free)
#define PITCH_B   272
#define PLANE_A   (64 * PITCH_B)    /* 17408 */
#define PLANE_W   (128 * PITCH_B)   /* 34816 */
#define OFF_SRC   0
#define OFF_DST   256
#define OFF_A     1024
#define OFF_B     (OFF_A + PLANE_A)              /* 18432 */
#define SMEM_TOTAL (OFF_B + PLANE_W)             /* 53248 -> 3 CTAs/SM */
#define OFF_STAGE OFF_A                          /* 32-row fp32 stage overlays A */
#define STAGE_PITCH 132

// Precomputed fp16 weight plane images: [5 weights][smem-image bytes]
__device__ __align__(16) char g_Wplanes[5][PLANE_W];

// ---------------- helpers ----------------------------------------------------
__device__ __forceinline__ uint32_t smem_u32(const void* p) {
    uint32_t a;
    asm("{ .reg .u64 t; cvta.to.shared.u64 t, %1; cvt.u32.u64 %0, t; }"
        : "=r"(a) : "l"(p));
    return a;
}

__device__ __forceinline__ void ldsm4(uint32_t* r, uint32_t addr) {
    asm volatile("ldmatrix.sync.aligned.m8n8.x4.shared.b16 {%0,%1,%2,%3}, [%4];"
                 : "=r"(r[0]), "=r"(r[1]), "=r"(r[2]), "=r"(r[3]) : "r"(addr));
}

__device__ __forceinline__ void mma16816(float* c, const uint32_t* a,
                                         uint32_t b0, uint32_t b1) {
    asm volatile(
        "mma.sync.aligned.m16n8k16.row.col.f32.f16.f16.f32 "
        "{%0,%1,%2,%3}, {%4,%5,%6,%7}, {%8,%9}, {%0,%1,%2,%3};"
        : "+f"(c[0]), "+f"(c[1]), "+f"(c[2]), "+f"(c[3])
        : "r"(a[0]), "r"(a[1]), "r"(a[2]), "r"(a[3]), "r"(b0), "r"(b1));
}

__device__ __forceinline__ void red_add4(float* p, float4 v) {
    asm volatile("red.global.add.v4.f32 [%0], {%1,%2,%3,%4};"
                 :: "l"(p), "f"(v.x), "f"(v.y), "f"(v.z), "f"(v.w) : "memory");
}

__device__ __forceinline__ float sigf(float x) {
    return __fdividef(1.f, 1.f + __expf(-x));
}

// convert one float4 (row r, float4-col c4) -> fp16 plane image
__device__ __forceinline__ void cvt_store16(char* plane, int r, int c4, float4 v) {
    __half2 a = __floats2half2_rn(v.x, v.y);
    __half2 b = __floats2half2_rn(v.z, v.w);
    uint32_t off = (uint32_t)r * PITCH_B + (uint32_t)c4 * 8;
    *reinterpret_cast<uint2*>(plane + off) =
        make_uint2(*reinterpret_cast<uint32_t*>(&a), *reinterpret_cast<uint32_t*>(&b));
}

// GEMM: acc += A . B^T  (64x128 tile, warp tile 32x32)
__device__ __forceinline__ void gemm_pass(uint32_t sb, int offA, int offB,
                                          int lane, int warp_m, int warp_n,
                                          float acc[2][4][4]) {
    uint32_t aBase = sb + offA +
        (uint32_t)((warp_m * 32 + (lane & 15)) * PITCH_B + (lane >> 4) * 16);
    uint32_t bBase = sb + offB +
        (uint32_t)((warp_n * 32 + (lane & 7) + (lane >> 4) * 8) * PITCH_B +
                   ((lane >> 3) & 1) * 16);
#pragma unroll
    for (int s = 0; s < 8; s++) {
        uint32_t a0[4], a1[4];
        ldsm4(a0, aBase + s * 32);
        ldsm4(a1, aBase + 16 * PITCH_B + s * 32);
#pragma unroll
        for (int ntp = 0; ntp < 2; ntp++) {
            uint32_t b[4];
            ldsm4(b, bBase + ntp * 16 * PITCH_B + s * 32);
            mma16816(acc[0][2 * ntp], a0, b[0], b[1]);
            mma16816(acc[0][2 * ntp + 1], a0, b[2], b[3]);
            mma16816(acc[1][2 * ntp], a1, b[0], b[1]);
            mma16816(acc[1][2 * ntp + 1], a1, b[2], b[3]);
        }
    }
}

// ---------------- K0: zero BN accumulators ----------------------------------
__global__ void init_stats_kernel() {
    int t = threadIdx.x;
    if (t < DD) { g_sum[t] = 0.f; g_sumsq[t] = 0.f; }
}

// ---------------- Kp: precompute fp16 W plane images (5 blocks) --------------
__global__ void __launch_bounds__(256)
prep_weights_kernel(const float* __restrict__ WA, const float* __restrict__ WB,
                    const float* __restrict__ WC, const float* __restrict__ WD,
                    const float* __restrict__ WE) {
    const float* Ws[5] = {WA, WB, WC, WD, WE};
    const float* __restrict__ W = Ws[blockIdx.x];
    char* P = g_Wplanes[blockIdx.x];
    for (int i = threadIdx.x; i < 128 * 32; i += 256) {
        int r = i >> 5, c4 = i & 31;
        float4 v = *(const float4*)&W[r * DD + c4 * 4];
        cvt_store16(P, r, c4, v);
    }
}

// copy precomputed W plane into smem (no math)
__device__ __forceinline__ void copy_w_plane(char* smem, int widx, int tid) {
    const float4* ws = (const float4*)g_Wplanes[widx];
    float4* bp = (float4*)(smem + OFF_B);
#pragma unroll 2
    for (int i = tid; i < PLANE_W / 16; i += 256) bp[i] = ws[i];
}

// ---------------- K1: node projections, 4 weights fused ----------------------
// WA -> ACh(Ah slots), WB -> Bhh, WC -> ACh(Ch slots), WD -> hpre (fp32)
__global__ void __launch_bounds__(256, 3)
node_gemm_kernel(const float* __restrict__ h) {
    extern __shared__ char smem[];
    const uint32_t sb = smem_u32(smem);
    const int tid = threadIdx.x;
    const int lane = tid & 31, wid = tid >> 5;
    const int warp_m = wid & 1, warp_n = wid >> 1;
    const int row0 = blockIdx.x * 64;

    // convert A tile (h rows) once
    for (int i = tid; i < 64 * 32; i += 256) {
        int r = i >> 5, c4 = i & 31;
        int grow = row0 + r;
        float4 v = make_float4(0.f, 0.f, 0.f, 0.f);
        if (grow < N_NODES) v = __ldcs((const float4*)&h[(size_t)grow * DD + c4 * 4]);
        cvt_store16(smem + OFF_A, r, c4, v);
    }

#pragma unroll 1
    for (int w = 0; w < 4; w++) {
        __syncthreads();   // prior readers of B plane done (and A fill for w=0)
        copy_w_plane(smem, w, tid);
        __syncthreads();

        float acc[2][4][4];
#pragma unroll
        for (int a = 0; a < 2; a++)
#pragma unroll
            for (int b = 0; b < 4; b++)
#pragma unroll
                for (int c = 0; c < 4; c++) acc[a][b][c] = 0.f;

        gemm_pass(sb, OFF_A, OFF_B, lane, warp_m, warp_n, acc);

#pragma unroll
        for (int mt = 0; mt < 2; mt++)
#pragma unroll
            for (int nt = 0; nt < 4; nt++) {
                int r = row0 + warp_m * 32 + mt * 16 + (lane >> 2);
                int c = warp_n * 32 + nt * 8 + (lane & 3) * 2;   // even
#pragma unroll
                for (int rr = 0; rr < 2; rr++) {
                    int row = r + rr * 8;
                    if (row >= N_NODES) continue;
                    float v0 = acc[mt][nt][2 * rr], v1 = acc[mt][nt][2 * rr + 1];
                    if (w == 3) {
                        *reinterpret_cast<float2*>(&g_hpre[(size_t)row * 128 + c]) =
                            make_float2(v0, v1);
                    } else {
                        __half2 hv = __floats2half2_rn(v0, v1);
                        if (w == 0)
                            *reinterpret_cast<__half2*>(
                                &g_ACh[(size_t)row * 256 + ((c >> 2) << 3) + (c & 3)]) = hv;
                        else if (w == 2)
                            *reinterpret_cast<__half2*>(
                                &g_ACh[(size_t)row * 256 + ((c >> 2) << 3) + (c & 3) + 4]) = hv;
                        else
                            *reinterpret_cast<__half2*>(&g_Bhh[(size_t)row * 128 + c]) = hv;
                    }
                }
            }
    }
}

// ---------------- K2: persistent edge GEMM + gate + message + scatter --------
__global__ void __launch_bounds__(256, 3)
edge_kernel(const float* __restrict__ e,
            const int* __restrict__ src, const int* __restrict__ dst,
            float* __restrict__ e_out) {
    extern __shared__ char smem[];
    const uint32_t sb = smem_u32(smem);
    const int tid = threadIdx.x;
    const int lane = tid & 31, wid = tid >> 5;
    const int warp_m = wid & 1, warp_n = wid >> 1;

    int* s_src = reinterpret_cast<int*>(smem + OFF_SRC);
    int* s_dst = reinterpret_cast<int*>(smem + OFF_DST);
    float* stage = reinterpret_cast<float*>(smem + OFF_STAGE);

    // WE plane: once per CTA (persistent)
    copy_w_plane(smem, 4, tid);

    for (int t = blockIdx.x; t < N_EDGES / 64; t += gridDim.x) {
        const int e0 = t * 64;
        if (tid < 64) s_src[tid] = src[e0 + tid];
        else if (tid < 128) s_dst[tid - 64] = dst[e0 + tid - 64];

        // convert e tile (streaming loads: evict-first, keep tables in L2)
        for (int i = tid; i < 64 * 32; i += 256) {
            int r = i >> 5, c4 = i & 31;
            float4 v = __ldcs((const float4*)&e[(size_t)(e0 + r) * DD + c4 * 4]);
            cvt_store16(smem + OFF_A, r, c4, v);
        }
        __syncthreads();   // A fill (+ W plane on first iter) visible

        float acc[2][4][4];
#pragma unroll
        for (int a = 0; a < 2; a++)
#pragma unroll
            for (int b = 0; b < 4; b++)
#pragma unroll
                for (int c = 0; c < 4; c++) acc[a][b][c] = 0.f;

        gemm_pass(sb, OFF_A, OFF_B, lane, warp_m, warp_n, acc);

        __syncthreads();   // all warps done reading A plane -> reuse as stage

        // two 32-row epilogue rounds (stage overlays the 17 KB A plane)
#pragma unroll 1
        for (int half = 0; half < 2; half++) {
            if (warp_m == half) {
#pragma unroll
                for (int mt = 0; mt < 2; mt++)
#pragma unroll
                    for (int nt = 0; nt < 4; nt++) {
                        int r = mt * 16 + (lane >> 2);
                        int c = warp_n * 32 + nt * 8 + (lane & 3) * 2;
                        *reinterpret_cast<float2*>(&stage[r * STAGE_PITCH + c]) =
                            make_float2(acc[mt][nt][0], acc[mt][nt][1]);
                        *reinterpret_cast<float2*>(&stage[(r + 8) * STAGE_PITCH + c]) =
                            make_float2(acc[mt][nt][2], acc[mt][nt][3]);
                    }
            }
            __syncthreads();

            // warp-per-edge: fp16 table gathers + fp32 vector reduction
#pragma unroll
            for (int i = 0; i < 4; i++) {
                int r32 = wid * 4 + i;
                int r = half * 32 + r32;
                float4 en = *reinterpret_cast<float4*>(&stage[r32 * STAGE_PITCH + 4 * lane]);
                int sn = s_src[r], dn = s_dst[r];
                uint4 acv = *reinterpret_cast<const uint4*>(&g_ACh[(size_t)sn * 256 + lane * 8]);
                const __half2* hp = reinterpret_cast<const __half2*>(&acv);
                float2 a01 = __half22float2(hp[0]), a23 = __half22float2(hp[1]);
                float2 c01 = __half22float2(hp[2]), c23 = __half22float2(hp[3]);
                uint2 bv = *reinterpret_cast<const uint2*>(&g_Bhh[(size_t)dn * 128 + 4 * lane]);
                const __half2* bp = reinterpret_cast<const __half2*>(&bv);
                float2 b01 = __half22float2(bp[0]), b23 = __half22float2(bp[1]);
                __stcs((float4*)&e_out[(size_t)(e0 + r) * DD + 4 * lane], en);
                float4 m;
                m.x = c01.x * sigf(a01.x + b01.x + en.x);
                m.y = c01.y * sigf(a01.y + b01.y + en.y);
                m.z = c23.x * sigf(a23.x + b23.x + en.z);
                m.w = c23.y * sigf(a23.y + b23.y + en.w);
                red_add4(&g_hpre[(size_t)dn * 128 + 4 * lane], m);
            }
            __syncthreads();   // stage reuse / next-tile A overwrite
        }
    }
}

// ---------------- K3a: BN stats over g_hpre ----------------------------------
__global__ void __launch_bounds__(256)
bn_stats_kernel() {
    __shared__ float4 ssum[256];
    __shared__ float4 ssq[256];
    const int l = threadIdx.x & 31;
    const int w = threadIdx.x >> 5;
    float4 s = make_float4(0.f, 0.f, 0.f, 0.f);
    float4 q = make_float4(0.f, 0.f, 0.f, 0.f);
    for (int r = blockIdx.x * 16 + w * 2; r < N_NODES; r += gridDim.x * 16) {
        float4 v = *(const float4*)&g_hpre[(size_t)r * 128 + 4 * l];
        float4 v2 = make_float4(0.f, 0.f, 0.f, 0.f);
        if (r + 1 < N_NODES)
            v2 = *(const float4*)&g_hpre[(size_t)(r + 1) * 128 + 4 * l];
        s.x += v.x + v2.x; s.y += v.y + v2.y; s.z += v.z + v2.z; s.w += v.w + v2.w;
        q.x += v.x * v.x + v2.x * v2.x; q.y += v.y * v.y + v2.y * v2.y;
        q.z += v.z * v.z + v2.z * v2.z; q.w += v.w * v.w + v2.w * v2.w;
    }
    ssum[threadIdx.x] = s;
    ssq[threadIdx.x] = q;
    __syncthreads();
    if (threadIdx.x < 32) {
        float4 S = ssum[l], Q = ssq[l];
        for (int ww = 1; ww < 8; ww++) {
            float4 t = ssum[ww * 32 + l];
            S.x += t.x; S.y += t.y; S.z += t.z; S.w += t.w;
            float4 u = ssq[ww * 32 + l];
            Q.x += u.x; Q.y += u.y; Q.z += u.z; Q.w += u.w;
        }
        atomicAdd(&g_sum[4 * l + 0], S.x); atomicAdd(&g_sum[4 * l + 1], S.y);
        atomicAdd(&g_sum[4 * l + 2], S.z); atomicAdd(&g_sum[4 * l + 3], S.w);
        atomicAdd(&g_sumsq[4 * l + 0], Q.x); atomicAdd(&g_sumsq[4 * l + 1], Q.y);
        atomicAdd(&g_sumsq[4 * l + 2], Q.z); atomicAdd(&g_sumsq[4 * l + 3], Q.w);
    }
}

// ---------------- K3b: normalize + affine + relu -----------------------------
__global__ void __launch_bounds__(256)
bn_apply_kernel(const float* __restrict__ gamma, const float* __restrict__ beta,
                float* __restrict__ h_out) {
    int idx4 = blockIdx.x * blockDim.x + threadIdx.x;
    if (idx4 >= N_NODES * DD / 4) return;
    int c4 = idx4 & 31;
    const float invN = 1.f / (float)N_NODES;
    float4 v = *(const float4*)&g_hpre[(size_t)idx4 * 4];
    float4 o;
#pragma unroll
    for (int k = 0; k < 4; k++) {
        float mean = g_sum[4 * c4 + k] * invN;
        float var = g_sumsq[4 * c4 + k] * invN - mean * mean;
        float x = ((&v.x)[k] - mean) * rsqrtf(var + BN_EPS) * gamma[4 * c4 + k] +
                  beta[4 * c4 + k];
        (&o.x)[k] = fmaxf(x, 0.f);
    }
    *reinterpret_cast<float4*>(&h_out[(size_t)idx4 * 4]) = o;
}

// -----------------------------------------------------------------------------
extern "C" void kernel_launch(void* const* d_in, const int* in_sizes, int n_in,
                              void* d_out, int out_size) {
    const float* h     = (const float*)d_in[0];
    const float* e     = (const float*)d_in[1];
    const float* WA    = (const float*)d_in[2];
    const float* WB    = (const float*)d_in[3];
    const float* WC    = (const float*)d_in[4];
    const float* WD    = (const float*)d_in[5];
    const float* WE    = (const float*)d_in[6];
    const float* gamma = (const float*)d_in[7];
    const float* beta  = (const float*)d_in[8];
    const int*   src   = (const int*)d_in[9];
    const int*   dst   = (const int*)d_in[10];

    float* h_out = (float*)d_out;
    float* e_out = (float*)d_out + (size_t)N_NODES * DD;

    cudaFuncSetAttribute(node_gemm_kernel, cudaFuncAttributeMaxDynamicSharedMemorySize, SMEM_TOTAL);
    cudaFuncSetAttribute(edge_kernel, cudaFuncAttributeMaxDynamicSharedMemorySize, SMEM_TOTAL);

    init_stats_kernel<<<1, 128>>>();
    prep_weights_kernel<<<5, 256>>>(WA, WB, WC, WD, WE);

    node_gemm_kernel<<<(N_NODES + 63) / 64, 256, SMEM_TOTAL>>>(h);

    edge_kernel<<<444, 256, SMEM_TOTAL>>>(e, src, dst, e_out);

    bn_stats_kernel<<<512, 256>>>();

    bn_apply_kernel<<<(N_NODES * DD / 4 + 255) / 256, 256>>>(gamma, beta, h_out);
}

// round 13
// speedup vs baseline: 4.8090x; 1.0348x over previous
#include <cuda_runtime.h>
#include <cuda_fp16.h>
#include <cstdint>

#define N_NODES 50000
#define N_EDGES 800000
#define DD 128
#define BN_EPS 1e-5f

// ---------------- scratch (static device memory; no runtime alloc) ----------
// g_ACh[node]: 256 halves = 32 groups of {Ah[4g..4g+3], Ch[4g..4g+3]}  (by src)
// g_Bhh[node]: 128 halves = Bh row                                      (by dst)
// g_hpre[node]: 128 floats = h@WD.T then += scatter(m)                  (by dst)
__device__ __align__(16) __half g_ACh[N_NODES * 256];
__device__ __align__(16) __half g_Bhh[N_NODES * 128];
__device__ __align__(16) float  g_hpre[N_NODES * 128];
__device__ float g_sum[DD];
__device__ float g_sumsq[DD];

// ---------------- smem layout ------------------------------------------------
// fp16 planes, K-major rows, pitch 136 halves = 272B (ldmatrix conflict-free)
#define PITCH_B   272
#define PLANE_A   (64 * PITCH_B)    /* 17408 */
#define PLANE_W   (128 * PITCH_B)   /* 34816 */
#define OFF_SRC   0
#define OFF_DST   256
#define OFF_A     1024
#define OFF_B     (OFF_A + PLANE_A)              /* 18432 */
#define SMEM_TOTAL (OFF_B + PLANE_W)             /* 53248 -> 4 CTAs/SM */
#define OFF_STAGE OFF_A                          /* 32-row fp32 stage overlays A */
#define STAGE_PITCH 132

// Precomputed fp16 weight plane images: [5 weights][smem-image bytes]
__device__ __align__(16) char g_Wplanes[5][PLANE_W];

// ---------------- helpers ----------------------------------------------------
__device__ __forceinline__ uint32_t smem_u32(const void* p) {
    uint32_t a;
    asm("{ .reg .u64 t; cvta.to.shared.u64 t, %1; cvt.u32.u64 %0, t; }"
        : "=r"(a) : "l"(p));
    return a;
}

__device__ __forceinline__ void ldsm4(uint32_t* r, uint32_t addr) {
    asm volatile("ldmatrix.sync.aligned.m8n8.x4.shared.b16 {%0,%1,%2,%3}, [%4];"
                 : "=r"(r[0]), "=r"(r[1]), "=r"(r[2]), "=r"(r[3]) : "r"(addr));
}

__device__ __forceinline__ void mma16816(float* c, const uint32_t* a,
                                         uint32_t b0, uint32_t b1) {
    asm volatile(
        "mma.sync.aligned.m16n8k16.row.col.f32.f16.f16.f32 "
        "{%0,%1,%2,%3}, {%4,%5,%6,%7}, {%8,%9}, {%0,%1,%2,%3};"
        : "+f"(c[0]), "+f"(c[1]), "+f"(c[2]), "+f"(c[3])
        : "r"(a[0]), "r"(a[1]), "r"(a[2]), "r"(a[3]), "r"(b0), "r"(b1));
}

__device__ __forceinline__ void red_add4(float* p, float4 v) {
    asm volatile("red.global.add.v4.f32 [%0], {%1,%2,%3,%4};"
                 :: "l"(p), "f"(v.x), "f"(v.y), "f"(v.z), "f"(v.w) : "memory");
}

__device__ __forceinline__ float sigf(float x) {
    return __fdividef(1.f, 1.f + __expf(-x));
}

// convert one float4 (row r, float4-col c4) -> fp16 plane image
__device__ __forceinline__ void cvt_store16(char* plane, int r, int c4, float4 v) {
    __half2 a = __floats2half2_rn(v.x, v.y);
    __half2 b = __floats2half2_rn(v.z, v.w);
    uint32_t off = (uint32_t)r * PITCH_B + (uint32_t)c4 * 8;
    *reinterpret_cast<uint2*>(plane + off) =
        make_uint2(*reinterpret_cast<uint32_t*>(&a), *reinterpret_cast<uint32_t*>(&b));
}

// GEMM: acc += A . B^T  (64x128 tile, warp tile 32x32)
__device__ __forceinline__ void gemm_pass(uint32_t sb, int offA, int offB,
                                          int lane, int warp_m, int warp_n,
                                          float acc[2][4][4]) {
    uint32_t aBase = sb + offA +
        (uint32_t)((warp_m * 32 + (lane & 15)) * PITCH_B + (lane >> 4) * 16);
    uint32_t bBase = sb + offB +
        (uint32_t)((warp_n * 32 + (lane & 7) + (lane >> 4) * 8) * PITCH_B +
                   ((lane >> 3) & 1) * 16);
#pragma unroll
    for (int s = 0; s < 8; s++) {
        uint32_t a0[4], a1[4];
        ldsm4(a0, aBase + s * 32);
        ldsm4(a1, aBase + 16 * PITCH_B + s * 32);
#pragma unroll
        for (int ntp = 0; ntp < 2; ntp++) {
            uint32_t b[4];
            ldsm4(b, bBase + ntp * 16 * PITCH_B + s * 32);
            mma16816(acc[0][2 * ntp], a0, b[0], b[1]);
            mma16816(acc[0][2 * ntp + 1], a0, b[2], b[3]);
            mma16816(acc[1][2 * ntp], a1, b[0], b[1]);
            mma16816(acc[1][2 * ntp + 1], a1, b[2], b[3]);
        }
    }
}

// ---------------- K0: zero BN accumulators ----------------------------------
__global__ void init_stats_kernel() {
    int t = threadIdx.x;
    if (t < DD) { g_sum[t] = 0.f; g_sumsq[t] = 0.f; }
}

// ---------------- Kp: precompute fp16 W plane images (5 blocks) --------------
__global__ void __launch_bounds__(256)
prep_weights_kernel(const float* __restrict__ WA, const float* __restrict__ WB,
                    const float* __restrict__ WC, const float* __restrict__ WD,
                    const float* __restrict__ WE) {
    const float* Ws[5] = {WA, WB, WC, WD, WE};
    const float* __restrict__ W = Ws[blockIdx.x];
    char* P = g_Wplanes[blockIdx.x];
    for (int i = threadIdx.x; i < 128 * 32; i += 256) {
        int r = i >> 5, c4 = i & 31;
        float4 v = *(const float4*)&W[r * DD + c4 * 4];
        cvt_store16(P, r, c4, v);
    }
}

// copy precomputed W plane into smem (no math)
__device__ __forceinline__ void copy_w_plane(char* smem, int widx, int tid) {
    const float4* ws = (const float4*)g_Wplanes[widx];
    float4* bp = (float4*)(smem + OFF_B);
#pragma unroll 2
    for (int i = tid; i < PLANE_W / 16; i += 256) bp[i] = ws[i];
}

// ---------------- K1: node projections, persistent per-weight CTAs -----------
// WA -> ACh(Ah slots), WB -> Bhh, WC -> ACh(Ch slots), WD -> hpre (fp32)
__global__ void __launch_bounds__(256, 4)
node_gemm_kernel(const float* __restrict__ h) {
    extern __shared__ char smem[];
    const uint32_t sb = smem_u32(smem);
    const int tid = threadIdx.x;
    const int lane = tid & 31, wid = tid >> 5;
    const int warp_m = wid & 1, warp_n = wid >> 1;
    const int w = blockIdx.x & 3;
    const int nTiles = (N_NODES + 63) / 64;

    // W plane: once per CTA (persistent per weight)
    copy_w_plane(smem, w, tid);

    for (int t = blockIdx.x >> 2; t < nTiles; t += gridDim.x >> 2) {
        const int row0 = t * 64;
        __syncthreads();   // W visible (1st iter) / prior gemm done reading A

        for (int i = tid; i < 64 * 32; i += 256) {
            int r = i >> 5, c4 = i & 31;
            int grow = row0 + r;
            float4 v = make_float4(0.f, 0.f, 0.f, 0.f);
            if (grow < N_NODES) v = *(const float4*)&h[(size_t)grow * DD + c4 * 4];
            cvt_store16(smem + OFF_A, r, c4, v);
        }
        __syncthreads();

        float acc[2][4][4];
#pragma unroll
        for (int a = 0; a < 2; a++)
#pragma unroll
            for (int b = 0; b < 4; b++)
#pragma unroll
                for (int c = 0; c < 4; c++) acc[a][b][c] = 0.f;

        gemm_pass(sb, OFF_A, OFF_B, lane, warp_m, warp_n, acc);

#pragma unroll
        for (int mt = 0; mt < 2; mt++)
#pragma unroll
            for (int nt = 0; nt < 4; nt++) {
                int r = row0 + warp_m * 32 + mt * 16 + (lane >> 2);
                int c = warp_n * 32 + nt * 8 + (lane & 3) * 2;   // even
#pragma unroll
                for (int rr = 0; rr < 2; rr++) {
                    int row = r + rr * 8;
                    if (row >= N_NODES) continue;
                    float v0 = acc[mt][nt][2 * rr], v1 = acc[mt][nt][2 * rr + 1];
                    if (w == 3) {
                        *reinterpret_cast<float2*>(&g_hpre[(size_t)row * 128 + c]) =
                            make_float2(v0, v1);
                    } else {
                        __half2 hv = __floats2half2_rn(v0, v1);
                        if (w == 0)
                            *reinterpret_cast<__half2*>(
                                &g_ACh[(size_t)row * 256 + ((c >> 2) << 3) + (c & 3)]) = hv;
                        else if (w == 2)
                            *reinterpret_cast<__half2*>(
                                &g_ACh[(size_t)row * 256 + ((c >> 2) << 3) + (c & 3) + 4]) = hv;
                        else
                            *reinterpret_cast<__half2*>(&g_Bhh[(size_t)row * 128 + c]) = hv;
                    }
                }
            }
    }
}

// ---------------- K2: persistent edge GEMM + gate + message + scatter --------
__global__ void __launch_bounds__(256, 4)
edge_kernel(const float* __restrict__ e,
            const int* __restrict__ src, const int* __restrict__ dst,
            float* __restrict__ e_out) {
    extern __shared__ char smem[];
    const uint32_t sb = smem_u32(smem);
    const int tid = threadIdx.x;
    const int lane = tid & 31, wid = tid >> 5;
    const int warp_m = wid & 1, warp_n = wid >> 1;

    int* s_src = reinterpret_cast<int*>(smem + OFF_SRC);
    int* s_dst = reinterpret_cast<int*>(smem + OFF_DST);
    float* stage = reinterpret_cast<float*>(smem + OFF_STAGE);

    // WE plane: once per CTA (persistent)
    copy_w_plane(smem, 4, tid);

    for (int t = blockIdx.x; t < N_EDGES / 64; t += gridDim.x) {
        const int e0 = t * 64;
        if (tid < 64) s_src[tid] = src[e0 + tid];
        else if (tid < 128) s_dst[tid - 64] = dst[e0 + tid - 64];

        // convert e tile (streaming loads: evict-first, keep tables in L2)
        for (int i = tid; i < 64 * 32; i += 256) {
            int r = i >> 5, c4 = i & 31;
            float4 v = __ldcs((const float4*)&e[(size_t)(e0 + r) * DD + c4 * 4]);
            cvt_store16(smem + OFF_A, r, c4, v);
        }
        __syncthreads();   // A fill (+ W plane on first iter) visible

        float acc[2][4][4];
#pragma unroll
        for (int a = 0; a < 2; a++)
#pragma unroll
            for (int b = 0; b < 4; b++)
#pragma unroll
                for (int c = 0; c < 4; c++) acc[a][b][c] = 0.f;

        gemm_pass(sb, OFF_A, OFF_B, lane, warp_m, warp_n, acc);

        __syncthreads();   // all warps done reading A plane -> reuse as stage

        // two 32-row epilogue rounds (stage overlays the 17 KB A plane)
#pragma unroll 1
        for (int half = 0; half < 2; half++) {
            if (warp_m == half) {
#pragma unroll
                for (int mt = 0; mt < 2; mt++)
#pragma unroll
                    for (int nt = 0; nt < 4; nt++) {
                        int r = mt * 16 + (lane >> 2);
                        int c = warp_n * 32 + nt * 8 + (lane & 3) * 2;
                        *reinterpret_cast<float2*>(&stage[r * STAGE_PITCH + c]) =
                            make_float2(acc[mt][nt][0], acc[mt][nt][1]);
                        *reinterpret_cast<float2*>(&stage[(r + 8) * STAGE_PITCH + c]) =
                            make_float2(acc[mt][nt][2], acc[mt][nt][3]);
                    }
            }
            __syncthreads();

            // warp-per-edge: fp16 table gathers + fp32 vector reduction
#pragma unroll
            for (int i = 0; i < 4; i++) {
                int r32 = wid * 4 + i;
                int r = half * 32 + r32;
                float4 en = *reinterpret_cast<float4*>(&stage[r32 * STAGE_PITCH + 4 * lane]);
                int sn = s_src[r], dn = s_dst[r];
                uint4 acv = *reinterpret_cast<const uint4*>(&g_ACh[(size_t)sn * 256 + lane * 8]);
                const __half2* hp = reinterpret_cast<const __half2*>(&acv);
                float2 a01 = __half22float2(hp[0]), a23 = __half22float2(hp[1]);
                float2 c01 = __half22float2(hp[2]), c23 = __half22float2(hp[3]);
                uint2 bv = *reinterpret_cast<const uint2*>(&g_Bhh[(size_t)dn * 128 + 4 * lane]);
                const __half2* bp = reinterpret_cast<const __half2*>(&bv);
                float2 b01 = __half22float2(bp[0]), b23 = __half22float2(bp[1]);
                __stcs((float4*)&e_out[(size_t)(e0 + r) * DD + 4 * lane], en);
                float4 m;
                m.x = c01.x * sigf(a01.x + b01.x + en.x);
                m.y = c01.y * sigf(a01.y + b01.y + en.y);
                m.z = c23.x * sigf(a23.x + b23.x + en.z);
                m.w = c23.y * sigf(a23.y + b23.y + en.w);
                red_add4(&g_hpre[(size_t)dn * 128 + 4 * lane], m);
            }
            __syncthreads();   // stage reuse / next-tile A overwrite
        }
    }
}

// ---------------- K3a: BN stats over g_hpre ----------------------------------
__global__ void __launch_bounds__(256)
bn_stats_kernel() {
    __shared__ float4 ssum[256];
    __shared__ float4 ssq[256];
    const int l = threadIdx.x & 31;
    const int w = threadIdx.x >> 5;
    float4 s = make_float4(0.f, 0.f, 0.f, 0.f);
    float4 q = make_float4(0.f, 0.f, 0.f, 0.f);
    for (int r = blockIdx.x * 16 + w * 2; r < N_NODES; r += gridDim.x * 16) {
        float4 v = *(const float4*)&g_hpre[(size_t)r * 128 + 4 * l];
        float4 v2 = make_float4(0.f, 0.f, 0.f, 0.f);
        if (r + 1 < N_NODES)
            v2 = *(const float4*)&g_hpre[(size_t)(r + 1) * 128 + 4 * l];
        s.x += v.x + v2.x; s.y += v.y + v2.y; s.z += v.z + v2.z; s.w += v.w + v2.w;
        q.x += v.x * v.x + v2.x * v2.x; q.y += v.y * v.y + v2.y * v2.y;
        q.z += v.z * v.z + v2.z * v2.z; q.w += v.w * v.w + v2.w * v2.w;
    }
    ssum[threadIdx.x] = s;
    ssq[threadIdx.x] = q;
    __syncthreads();
    if (threadIdx.x < 32) {
        float4 S = ssum[l], Q = ssq[l];
        for (int ww = 1; ww < 8; ww++) {
            float4 t = ssum[ww * 32 + l];
            S.x += t.x; S.y += t.y; S.z += t.z; S.w += t.w;
            float4 u = ssq[ww * 32 + l];
            Q.x += u.x; Q.y += u.y; Q.z += u.z; Q.w += u.w;
        }
        atomicAdd(&g_sum[4 * l + 0], S.x); atomicAdd(&g_sum[4 * l + 1], S.y);
        atomicAdd(&g_sum[4 * l + 2], S.z); atomicAdd(&g_sum[4 * l + 3], S.w);
        atomicAdd(&g_sumsq[4 * l + 0], Q.x); atomicAdd(&g_sumsq[4 * l + 1], Q.y);
        atomicAdd(&g_sumsq[4 * l + 2], Q.z); atomicAdd(&g_sumsq[4 * l + 3], Q.w);
    }
}

// ---------------- K3b: normalize + affine + relu -----------------------------
__global__ void __launch_bounds__(256)
bn_apply_kernel(const float* __restrict__ gamma, const float* __restrict__ beta,
                float* __restrict__ h_out) {
    int idx4 = blockIdx.x * blockDim.x + threadIdx.x;
    if (idx4 >= N_NODES * DD / 4) return;
    int c4 = idx4 & 31;
    const float invN = 1.f / (float)N_NODES;
    float4 v = *(const float4*)&g_hpre[(size_t)idx4 * 4];
    float4 o;
#pragma unroll
    for (int k = 0; k < 4; k++) {
        float mean = g_sum[4 * c4 + k] * invN;
        float var = g_sumsq[4 * c4 + k] * invN - mean * mean;
        float x = ((&v.x)[k] - mean) * rsqrtf(var + BN_EPS) * gamma[4 * c4 + k] +
                  beta[4 * c4 + k];
        (&o.x)[k] = fmaxf(x, 0.f);
    }
    *reinterpret_cast<float4*>(&h_out[(size_t)idx4 * 4]) = o;
}

// -----------------------------------------------------------------------------
extern "C" void kernel_launch(void* const* d_in, const int* in_sizes, int n_in,
                              void* d_out, int out_size) {
    const float* h     = (const float*)d_in[0];
    const float* e     = (const float*)d_in[1];
    const float* WA    = (const float*)d_in[2];
    const float* WB    = (const float*)d_in[3];
    const float* WC    = (const float*)d_in[4];
    const float* WD    = (const float*)d_in[5];
    const float* WE    = (const float*)d_in[6];
    const float* gamma = (const float*)d_in[7];
    const float* beta  = (const float*)d_in[8];
    const int*   src   = (const int*)d_in[9];
    const int*   dst   = (const int*)d_in[10];

    float* h_out = (float*)d_out;
    float* e_out = (float*)d_out + (size_t)N_NODES * DD;

    cudaFuncSetAttribute(node_gemm_kernel, cudaFuncAttributeMaxDynamicSharedMemorySize, SMEM_TOTAL);
    cudaFuncSetAttribute(edge_kernel, cudaFuncAttributeMaxDynamicSharedMemorySize, SMEM_TOTAL);

    init_stats_kernel<<<1, 128>>>();
    prep_weights_kernel<<<5, 256>>>(WA, WB, WC, WD, WE);

    node_gemm_kernel<<<592, 256, SMEM_TOTAL>>>(h);

    edge_kernel<<<592, 256, SMEM_TOTAL>>>(e, src, dst, e_out);

    bn_stats_kernel<<<512, 256>>>();

    bn_apply_kernel<<<(N_NODES * DD / 4 + 255) / 256, 256>>>(gamma, beta, h_out);
}

// round 17
// speedup vs baseline: 4.8642x; 1.0115x over previous
#include <cuda_runtime.h>
#include <cuda_fp16.h>
#include <cstdint>

#define N_NODES 50000
#define N_EDGES 800000
#define DD 128
#define BN_EPS 1e-5f

// ---------------- scratch (static device memory; no runtime alloc) ----------
// g_ACh[node]: 256 halves = 32 groups of {Ah[4g..4g+3], Ch[4g..4g+3]}  (by src)
// g_Bhh[node]: 128 halves = Bh row                                      (by dst)
// g_hpre[node]: 128 floats = h@WD.T then += scatter(m)                  (by dst)
__device__ __align__(16) __half g_ACh[N_NODES * 256];
__device__ __align__(16) __half g_Bhh[N_NODES * 128];
__device__ __align__(16) float  g_hpre[N_NODES * 128];
__device__ float g_sum[DD];
__device__ float g_sumsq[DD];

// ---------------- smem layout ------------------------------------------------
// fp16 planes, K-major rows, pitch 136 halves = 272B (ldmatrix conflict-free)
#define PITCH_B   272
#define PLANE_A   (64 * PITCH_B)    /* 17408 */
#define PLANE_W   (128 * PITCH_B)   /* 34816 */
#define OFF_SRC   0
#define OFF_DST   256
#define OFF_A     1024
#define OFF_B     (OFF_A + PLANE_A)              /* 18432 */
#define SMEM_TOTAL (OFF_B + PLANE_W)             /* 53248 -> 4 CTAs/SM */
#define OFF_STAGE OFF_A                          /* 32-row fp32 stage overlays A */
#define STAGE_PITCH 132

// Precomputed fp16 weight plane images: [5 weights][smem-image bytes]
__device__ __align__(16) char g_Wplanes[5][PLANE_W];

// ---------------- helpers ----------------------------------------------------
__device__ __forceinline__ uint32_t smem_u32(const void* p) {
    uint32_t a;
    asm("{ .reg .u64 t; cvta.to.shared.u64 t, %1; cvt.u32.u64 %0, t; }"
        : "=r"(a) : "l"(p));
    return a;
}

__device__ __forceinline__ void ldsm4(uint32_t* r, uint32_t addr) {
    asm volatile("ldmatrix.sync.aligned.m8n8.x4.shared.b16 {%0,%1,%2,%3}, [%4];"
                 : "=r"(r[0]), "=r"(r[1]), "=r"(r[2]), "=r"(r[3]) : "r"(addr));
}

__device__ __forceinline__ void mma16816(float* c, const uint32_t* a,
                                         uint32_t b0, uint32_t b1) {
    asm volatile(
        "mma.sync.aligned.m16n8k16.row.col.f32.f16.f16.f32 "
        "{%0,%1,%2,%3}, {%4,%5,%6,%7}, {%8,%9}, {%0,%1,%2,%3};"
        : "+f"(c[0]), "+f"(c[1]), "+f"(c[2]), "+f"(c[3])
        : "r"(a[0]), "r"(a[1]), "r"(a[2]), "r"(a[3]), "r"(b0), "r"(b1));
}

__device__ __forceinline__ void red_add4(float* p, float4 v) {
    asm volatile("red.global.add.v4.f32 [%0], {%1,%2,%3,%4};"
                 :: "l"(p), "f"(v.x), "f"(v.y), "f"(v.z), "f"(v.w) : "memory");
}

// sigmoid via MUFU.TANH: sig(x) = 0.5*tanh(x/2) + 0.5  (1 MUFU + FMA)
__device__ __forceinline__ float sigf(float x) {
    float t;
    asm("tanh.approx.f32 %0, %1;" : "=f"(t) : "f"(x * 0.5f));
    return fmaf(t, 0.5f, 0.5f);
}

// convert one float4 (row r, float4-col c4) -> fp16 plane image
__device__ __forceinline__ void cvt_store16(char* plane, int r, int c4, float4 v) {
    __half2 a = __floats2half2_rn(v.x, v.y);
    __half2 b = __floats2half2_rn(v.z, v.w);
    uint32_t off = (uint32_t)r * PITCH_B + (uint32_t)c4 * 8;
    *reinterpret_cast<uint2*>(plane + off) =
        make_uint2(*reinterpret_cast<uint32_t*>(&a), *reinterpret_cast<uint32_t*>(&b));
}

// GEMM: acc += A . B^T  (64x128 tile, warp tile 32x32)
__device__ __forceinline__ void gemm_pass(uint32_t sb, int offA, int offB,
                                          int lane, int warp_m, int warp_n,
                                          float acc[2][4][4]) {
    uint32_t aBase = sb + offA +
        (uint32_t)((warp_m * 32 + (lane & 15)) * PITCH_B + (lane >> 4) * 16);
    uint32_t bBase = sb + offB +
        (uint32_t)((warp_n * 32 + (lane & 7) + (lane >> 4) * 8) * PITCH_B +
                   ((lane >> 3) & 1) * 16);
#pragma unroll
    for (int s = 0; s < 8; s++) {
        uint32_t a0[4], a1[4];
        ldsm4(a0, aBase + s * 32);
        ldsm4(a1, aBase + 16 * PITCH_B + s * 32);
#pragma unroll
        for (int ntp = 0; ntp < 2; ntp++) {
            uint32_t b[4];
            ldsm4(b, bBase + ntp * 16 * PITCH_B + s * 32);
            mma16816(acc[0][2 * ntp], a0, b[0], b[1]);
            mma16816(acc[0][2 * ntp + 1], a0, b[2], b[3]);
            mma16816(acc[1][2 * ntp], a1, b[0], b[1]);
            mma16816(acc[1][2 * ntp + 1], a1, b[2], b[3]);
        }
    }
}

// ---------------- K0: zero BN accumulators ----------------------------------
__global__ void init_stats_kernel() {
    int t = threadIdx.x;
    if (t < DD) { g_sum[t] = 0.f; g_sumsq[t] = 0.f; }
}

// ---------------- Kp: precompute fp16 W plane images (5 blocks) --------------
__global__ void __launch_bounds__(256)
prep_weights_kernel(const float* __restrict__ WA, const float* __restrict__ WB,
                    const float* __restrict__ WC, const float* __restrict__ WD,
                    const float* __restrict__ WE) {
    const float* Ws[5] = {WA, WB, WC, WD, WE};
    const float* __restrict__ W = Ws[blockIdx.x];
    char* P = g_Wplanes[blockIdx.x];
    for (int i = threadIdx.x; i < 128 * 32; i += 256) {
        int r = i >> 5, c4 = i & 31;
        float4 v = *(const float4*)&W[r * DD + c4 * 4];
        cvt_store16(P, r, c4, v);
    }
}

// copy precomputed W plane into smem (no math)
__device__ __forceinline__ void copy_w_plane(char* smem, int widx, int tid) {
    const float4* ws = (const float4*)g_Wplanes[widx];
    float4* bp = (float4*)(smem + OFF_B);
#pragma unroll 2
    for (int i = tid; i < PLANE_W / 16; i += 256) bp[i] = ws[i];
}

// ---------------- K1: node projections, persistent per-weight CTAs -----------
// WA -> ACh(Ah slots), WB -> Bhh, WC -> ACh(Ch slots), WD -> hpre (fp32)
__global__ void __launch_bounds__(256, 4)
node_gemm_kernel(const float* __restrict__ h) {
    extern __shared__ char smem[];
    const uint32_t sb = smem_u32(smem);
    const int tid = threadIdx.x;
    const int lane = tid & 31, wid = tid >> 5;
    const int warp_m = wid & 1, warp_n = wid >> 1;
    const int w = blockIdx.x & 3;
    const int nTiles = (N_NODES + 63) / 64;

    // W plane: once per CTA (persistent per weight)
    copy_w_plane(smem, w, tid);

    for (int t = blockIdx.x >> 2; t < nTiles; t += gridDim.x >> 2) {
        const int row0 = t * 64;
        __syncthreads();   // W visible (1st iter) / prior gemm done reading A

        for (int i = tid; i < 64 * 32; i += 256) {
            int r = i >> 5, c4 = i & 31;
            int grow = row0 + r;
            float4 v = make_float4(0.f, 0.f, 0.f, 0.f);
            if (grow < N_NODES) v = *(const float4*)&h[(size_t)grow * DD + c4 * 4];
            cvt_store16(smem + OFF_A, r, c4, v);
        }
        __syncthreads();

        float acc[2][4][4];
#pragma unroll
        for (int a = 0; a < 2; a++)
#pragma unroll
            for (int b = 0; b < 4; b++)
#pragma unroll
                for (int c = 0; c < 4; c++) acc[a][b][c] = 0.f;

        gemm_pass(sb, OFF_A, OFF_B, lane, warp_m, warp_n, acc);

#pragma unroll
        for (int mt = 0; mt < 2; mt++)
#pragma unroll
            for (int nt = 0; nt < 4; nt++) {
                int r = row0 + warp_m * 32 + mt * 16 + (lane >> 2);
                int c = warp_n * 32 + nt * 8 + (lane & 3) * 2;   // even
#pragma unroll
                for (int rr = 0; rr < 2; rr++) {
                    int row = r + rr * 8;
                    if (row >= N_NODES) continue;
                    float v0 = acc[mt][nt][2 * rr], v1 = acc[mt][nt][2 * rr + 1];
                    if (w == 3) {
                        *reinterpret_cast<float2*>(&g_hpre[(size_t)row * 128 + c]) =
                            make_float2(v0, v1);
                    } else {
                        __half2 hv = __floats2half2_rn(v0, v1);
                        if (w == 0)
                            *reinterpret_cast<__half2*>(
                                &g_ACh[(size_t)row * 256 + ((c >> 2) << 3) + (c & 3)]) = hv;
                        else if (w == 2)
                            *reinterpret_cast<__half2*>(
                                &g_ACh[(size_t)row * 256 + ((c >> 2) << 3) + (c & 3) + 4]) = hv;
                        else
                            *reinterpret_cast<__half2*>(&g_Bhh[(size_t)row * 128 + c]) = hv;
                    }
                }
            }
    }
}

// ---------------- K2: persistent edge GEMM + gate + message + scatter --------
__global__ void __launch_bounds__(256, 4)
edge_kernel(const float* __restrict__ e,
            const int* __restrict__ src, const int* __restrict__ dst,
            float* __restrict__ e_out) {
    extern __shared__ char smem[];
    const uint32_t sb = smem_u32(smem);
    const int tid = threadIdx.x;
    const int lane = tid & 31, wid = tid >> 5;
    const int warp_m = wid & 1, warp_n = wid >> 1;

    int* s_src = reinterpret_cast<int*>(smem + OFF_SRC);
    int* s_dst = reinterpret_cast<int*>(smem + OFF_DST);
    float* stage = reinterpret_cast<float*>(smem + OFF_STAGE);

    // WE plane: once per CTA (persistent)
    copy_w_plane(smem, 4, tid);

    for (int t = blockIdx.x; t < N_EDGES / 64; t += gridDim.x) {
        const int e0 = t * 64;
        if (tid < 64) s_src[tid] = src[e0 + tid];
        else if (tid < 128) s_dst[tid - 64] = dst[e0 + tid - 64];

        // convert e tile (streaming loads: evict-first, keep tables in L2)
        for (int i = tid; i < 64 * 32; i += 256) {
            int r = i >> 5, c4 = i & 31;
            float4 v = __ldcs((const float4*)&e[(size_t)(e0 + r) * DD + c4 * 4]);
            cvt_store16(smem + OFF_A, r, c4, v);
        }
        __syncthreads();   // A fill (+ W plane on first iter) visible

        float acc[2][4][4];
#pragma unroll
        for (int a = 0; a < 2; a++)
#pragma unroll
            for (int b = 0; b < 4; b++)
#pragma unroll
                for (int c = 0; c < 4; c++) acc[a][b][c] = 0.f;

        gemm_pass(sb, OFF_A, OFF_B, lane, warp_m, warp_n, acc);

        __syncthreads();   // all warps done reading A plane -> reuse as stage

        // two 32-row epilogue rounds (stage overlays the 17 KB A plane)
#pragma unroll 1
        for (int half = 0; half < 2; half++) {
            if (warp_m == half) {
#pragma unroll
                for (int mt = 0; mt < 2; mt++)
#pragma unroll
                    for (int nt = 0; nt < 4; nt++) {
                        int r = mt * 16 + (lane >> 2);
                        int c = warp_n * 32 + nt * 8 + (lane & 3) * 2;
                        *reinterpret_cast<float2*>(&stage[r * STAGE_PITCH + c]) =
                            make_float2(acc[mt][nt][0], acc[mt][nt][1]);
                        *reinterpret_cast<float2*>(&stage[(r + 8) * STAGE_PITCH + c]) =
                            make_float2(acc[mt][nt][2], acc[mt][nt][3]);
                    }
            }
            __syncthreads();

            // warp-per-edge: fp16 table gathers + fp32 vector reduction
#pragma unroll
            for (int i = 0; i < 4; i++) {
                int r32 = wid * 4 + i;
                int r = half * 32 + r32;
                float4 en = *reinterpret_cast<float4*>(&stage[r32 * STAGE_PITCH + 4 * lane]);
                int sn = s_src[r], dn = s_dst[r];
                uint4 acv = *reinterpret_cast<const uint4*>(&g_ACh[(size_t)sn * 256 + lane * 8]);
                const __half2* hp = reinterpret_cast<const __half2*>(&acv);
                float2 a01 = __half22float2(hp[0]), a23 = __half22float2(hp[1]);
                float2 c01 = __half22float2(hp[2]), c23 = __half22float2(hp[3]);
                uint2 bv = *reinterpret_cast<const uint2*>(&g_Bhh[(size_t)dn * 128 + 4 * lane]);
                const __half2* bp = reinterpret_cast<const __half2*>(&bv);
                float2 b01 = __half22float2(bp[0]), b23 = __half22float2(bp[1]);
                __stcs((float4*)&e_out[(size_t)(e0 + r) * DD + 4 * lane], en);
                float4 m;
                m.x = c01.x * sigf(a01.x + b01.x + en.x);
                m.y = c01.y * sigf(a01.y + b01.y + en.y);
                m.z = c23.x * sigf(a23.x + b23.x + en.z);
                m.w = c23.y * sigf(a23.y + b23.y + en.w);
                red_add4(&g_hpre[(size_t)dn * 128 + 4 * lane], m);
            }
            __syncthreads();   // stage reuse / next-tile A overwrite
        }
    }
}

// ---------------- K3a: BN stats over g_hpre (8-deep MLP) ---------------------
__global__ void __launch_bounds__(256)
bn_stats_kernel() {
    __shared__ float4 ssum[256];
    __shared__ float4 ssq[256];
    const int c4 = threadIdx.x & 31;
    const int w = threadIdx.x >> 5;
    float4 s = make_float4(0.f, 0.f, 0.f, 0.f);
    float4 q = make_float4(0.f, 0.f, 0.f, 0.f);
    for (int r0 = blockIdx.x * 64 + w * 8; r0 < N_NODES; r0 += gridDim.x * 64) {
#pragma unroll
        for (int i = 0; i < 8; i++) {
            int r = r0 + i;
            if (r < N_NODES) {
                float4 v = *(const float4*)&g_hpre[(size_t)r * 128 + 4 * c4];
                s.x += v.x; s.y += v.y; s.z += v.z; s.w += v.w;
                q.x += v.x * v.x; q.y += v.y * v.y;
                q.z += v.z * v.z; q.w += v.w * v.w;
            }
        }
    }
    ssum[threadIdx.x] = s;
    ssq[threadIdx.x] = q;
    __syncthreads();
    if (threadIdx.x < 32) {
        float4 S = ssum[c4], Q = ssq[c4];
        for (int ww = 1; ww < 8; ww++) {
            float4 t = ssum[ww * 32 + c4];
            S.x += t.x; S.y += t.y; S.z += t.z; S.w += t.w;
            float4 u = ssq[ww * 32 + c4];
            Q.x += u.x; Q.y += u.y; Q.z += u.z; Q.w += u.w;
        }
        atomicAdd(&g_sum[4 * c4 + 0], S.x); atomicAdd(&g_sum[4 * c4 + 1], S.y);
        atomicAdd(&g_sum[4 * c4 + 2], S.z); atomicAdd(&g_sum[4 * c4 + 3], S.w);
        atomicAdd(&g_sumsq[4 * c4 + 0], Q.x); atomicAdd(&g_sumsq[4 * c4 + 1], Q.y);
        atomicAdd(&g_sumsq[4 * c4 + 2], Q.z); atomicAdd(&g_sumsq[4 * c4 + 3], Q.w);
    }
}

// ---------------- K3b: normalize + affine + relu (2 float4 per thread) -------
__global__ void __launch_bounds__(256)
bn_apply_kernel(const float* __restrict__ gamma, const float* __restrict__ beta,
                float* __restrict__ h_out) {
    int base = (blockIdx.x * blockDim.x + threadIdx.x) * 2;
    const float invN = 1.f / (float)N_NODES;
#pragma unroll
    for (int u = 0; u < 2; u++) {
        int idx4 = base + u;
        if (idx4 >= N_NODES * DD / 4) return;
        int c4 = idx4 & 31;
        float4 v = *(const float4*)&g_hpre[(size_t)idx4 * 4];
        float4 o;
#pragma unroll
        for (int k = 0; k < 4; k++) {
            float mean = g_sum[4 * c4 + k] * invN;
            float var = g_sumsq[4 * c4 + k] * invN - mean * mean;
            float x = ((&v.x)[k] - mean) * rsqrtf(var + BN_EPS) * gamma[4 * c4 + k] +
                      beta[4 * c4 + k];
            (&o.x)[k] = fmaxf(x, 0.f);
        }
        __stcs((float4*)&h_out[(size_t)idx4 * 4], o);
    }
}

// -----------------------------------------------------------------------------
extern "C" void kernel_launch(void* const* d_in, const int* in_sizes, int n_in,
                              void* d_out, int out_size) {
    const float* h     = (const float*)d_in[0];
    const float* e     = (const float*)d_in[1];
    const float* WA    = (const float*)d_in[2];
    const float* WB    = (const float*)d_in[3];
    const float* WC    = (const float*)d_in[4];
    const float* WD    = (const float*)d_in[5];
    const float* WE    = (const float*)d_in[6];
    const float* gamma = (const float*)d_in[7];
    const float* beta  = (const float*)d_in[8];
    const int*   src   = (const int*)d_in[9];
    const int*   dst   = (const int*)d_in[10];

    float* h_out = (float*)d_out;
    float* e_out = (float*)d_out + (size_t)N_NODES * DD;

    cudaFuncSetAttribute(node_gemm_kernel, cudaFuncAttributeMaxDynamicSharedMemorySize, SMEM_TOTAL);
    cudaFuncSetAttribute(edge_kernel, cudaFuncAttributeMaxDynamicSharedMemorySize, SMEM_TOTAL);

    init_stats_kernel<<<1, 128>>>();
    prep_weights_kernel<<<5, 256>>>(WA, WB, WC, WD, WE);

    node_gemm_kernel<<<592, 256, SMEM_TOTAL>>>(h);

    edge_kernel<<<592, 256, SMEM_TOTAL>>>(e, src, dst, e_out);

    bn_stats_kernel<<<392, 256>>>();

    bn_apply_kernel<<<(N_NODES * DD / 8 + 255) / 256, 256>>>(gamma, beta, h_out);
}